// round 10
// baseline (speedup 1.0000x reference)
#include <cuda_runtime.h>
#include <cuda_bf16.h>
#include <cstdint>
#include <math.h>

#define BATCH 2
#define SEQ   2048
#define EMB   1024
#define HEADS 16
#define HDIM  64
#define NROWS (BATCH*SEQ)

// ---------------- scratch (__device__ globals; no allocs allowed) -----------
__device__ __nv_bfloat16 g_xh[NROWS*EMB], g_xl[NROWS*EMB];
__device__ __nv_bfloat16 g_ch[NROWS*EMB], g_cl[NROWS*EMB];
__device__ __nv_bfloat16 g_wh[4][EMB*EMB], g_wl[4][EMB*EMB];
__device__ __nv_bfloat16 g_qh[NROWS*EMB], g_ql[NROWS*EMB];
__device__ __nv_bfloat16 g_kh[NROWS*EMB], g_kl[NROWS*EMB];
__device__ __nv_bfloat16 g_vh[NROWS*EMB], g_vl[NROWS*EMB];

// ---------------- helpers ----------------------------------------------------
__device__ __forceinline__ uint32_t smem_u32(const void* p) {
    uint32_t a;
    asm("{ .reg .u64 t; cvta.to.shared.u64 t, %1; cvt.u32.u64 %0, t; }" : "=r"(a) : "l"(p));
    return a;
}
__device__ __forceinline__ void mma16816(float* c, const uint32_t* a,
                                         uint32_t b0, uint32_t b1) {
    asm volatile(
        "mma.sync.aligned.m16n8k16.row.col.f32.bf16.bf16.f32 "
        "{%0,%1,%2,%3}, {%4,%5,%6,%7}, {%8,%9}, {%0,%1,%2,%3};"
        : "+f"(c[0]), "+f"(c[1]), "+f"(c[2]), "+f"(c[3])
        : "r"(a[0]), "r"(a[1]), "r"(a[2]), "r"(a[3]), "r"(b0), "r"(b1));
}
__device__ __forceinline__ void ldsm4t(uint32_t& r0, uint32_t& r1,
                                       uint32_t& r2, uint32_t& r3, uint32_t addr) {
    asm volatile("ldmatrix.sync.aligned.m8n8.x4.trans.shared.b16 {%0,%1,%2,%3}, [%4];"
        : "=r"(r0), "=r"(r1), "=r"(r2), "=r"(r3) : "r"(addr));
}
__device__ __forceinline__ void cp16(uint32_t dst, const void* src) {
    asm volatile("cp.async.cg.shared.global [%0], [%1], 16;" :: "r"(dst), "l"(src) : "memory");
}
#define CP_COMMIT() asm volatile("cp.async.commit_group;" ::: "memory")
#define CP_WAIT1()  asm volatile("cp.async.wait_group 1;" ::: "memory")
#define CP_WAIT0()  asm volatile("cp.async.wait_group 0;" ::: "memory")

__device__ __forceinline__ uint32_t packbf(float lo, float hi) {
    __nv_bfloat162 t = __floats2bfloat162_rn(lo, hi);
    return *reinterpret_cast<uint32_t*>(&t);
}
__device__ __forceinline__ void store_split(__nv_bfloat16* oh, __nv_bfloat16* ol,
                                            size_t idx, float v0, float v1) {
    __nv_bfloat16 h0 = __float2bfloat16_rn(v0), h1 = __float2bfloat16_rn(v1);
    *(__nv_bfloat162*)(oh + idx) = __nv_bfloat162(h0, h1);
    *(__nv_bfloat162*)(ol + idx) = __nv_bfloat162(
        __float2bfloat16_rn(v0 - __bfloat162float(h0)),
        __float2bfloat16_rn(v1 - __bfloat162float(h1)));
}

// ---------------------------------------------------------------------------
// fused split: x + 4 weights in ONE launch
// ---------------------------------------------------------------------------
#define NX4 (NROWS*EMB/4)     // 1048576
#define NW4 (EMB*EMB/4)       // 262144 = 2^18

__global__ __launch_bounds__(256) void split_all(const float4* __restrict__ x,
                                                 const float4* __restrict__ w0,
                                                 const float4* __restrict__ w1,
                                                 const float4* __restrict__ w2,
                                                 const float4* __restrict__ w3,
                                                 __nv_bfloat162* __restrict__ xh,
                                                 __nv_bfloat162* __restrict__ xl,
                                                 __nv_bfloat162* __restrict__ wh,
                                                 __nv_bfloat162* __restrict__ wl) {
    int i = blockIdx.x * blockDim.x + threadIdx.x;
    const float4* src; __nv_bfloat162* oh; __nv_bfloat162* ol; int idx;
    if (i < NX4) {
        src = x; oh = xh; ol = xl; idx = i;
    } else {
        int j = i - NX4;
        int wsel = j >> 18;
        idx = j & (NW4 - 1);
        src = (wsel == 0) ? w0 : (wsel == 1) ? w1 : (wsel == 2) ? w2 : w3;
        oh = wh + (size_t)wsel * (EMB*EMB/2);
        ol = wl + (size_t)wsel * (EMB*EMB/2);
    }
    float4 a = src[idx];
    __nv_bfloat16 h0 = __float2bfloat16_rn(a.x);
    __nv_bfloat16 h1 = __float2bfloat16_rn(a.y);
    __nv_bfloat16 h2 = __float2bfloat16_rn(a.z);
    __nv_bfloat16 h3 = __float2bfloat16_rn(a.w);
    oh[idx*2+0] = __nv_bfloat162(h0, h1);
    oh[idx*2+1] = __nv_bfloat162(h2, h3);
    ol[idx*2+0] = __nv_bfloat162(__float2bfloat16_rn(a.x - __bfloat162float(h0)),
                                 __float2bfloat16_rn(a.y - __bfloat162float(h1)));
    ol[idx*2+1] = __nv_bfloat162(__float2bfloat16_rn(a.z - __bfloat162float(h2)),
                                 __float2bfloat16_rn(a.w - __bfloat162float(h3)));
}

// ---------------------------------------------------------------------------
// GEMM core: 128x128 CTA, 8 warps (4m x 2n), warp tile 32x64.
// k-chunk 32, pitch 80B, cp.async double buffer, 2 CTAs/SM. Scalar frag loads.
// ---------------------------------------------------------------------------
#define GPB2 80
#define GT_TILE  (128*GPB2)         // 10240
#define GT_STAGE (4*GT_TILE)        // 40960
#define GT_SMEM  (2*GT_STAGE)       // 81920

__device__ __forceinline__ void gemm_core(const __nv_bfloat16* __restrict__ Ah,
                                          const __nv_bfloat16* __restrict__ Al,
                                          const __nv_bfloat16* __restrict__ Bh,
                                          const __nv_bfloat16* __restrict__ Bl,
                                          char* sm, uint32_t smb,
                                          int m0, int n0, float acc[2][8][4]) {
    const int tid = threadIdx.x;
    const int w = tid >> 5, lane = tid & 31, g = lane >> 2, t4 = lane & 3;
    const int wm = w & 3, wn = w >> 2;

    const char* gsrc[4] = { (const char*)(Ah + (size_t)m0 * EMB),
                            (const char*)(Al + (size_t)m0 * EMB),
                            (const char*)(Bh + (size_t)n0 * EMB),
                            (const char*)(Bl + (size_t)n0 * EMB) };

    auto issue = [&](int kc, int stg) {
        uint32_t dstb = smb + stg * GT_STAGE;
        #pragma unroll
        for (int mX = 0; mX < 4; mX++) {
            #pragma unroll
            for (int j = 0; j < 2; j++) {
                int idx = tid + j * 256;            // 0..511
                int r = idx >> 2, c = idx & 3;
                cp16(dstb + mX*GT_TILE + r*GPB2 + c*16,
                     gsrc[mX] + kc*64 + (size_t)r*2048 + c*16);
            }
        }
        CP_COMMIT();
    };

    issue(0, 0);
    for (int kc = 0; kc < 32; kc++) {
        int cur = kc & 1;
        if (kc < 31) { issue(kc + 1, cur ^ 1); CP_WAIT1(); }
        else         { CP_WAIT0(); }
        __syncthreads();

        char* SAH = sm + cur*GT_STAGE;
        char* SAL = SAH + GT_TILE;
        char* SBH = SAH + 2*GT_TILE;
        char* SBL = SAH + 3*GT_TILE;

        #pragma unroll
        for (int ks = 0; ks < 2; ks++) {
            uint32_t ah[2][4], al[2][4];
            #pragma unroll
            for (int mt = 0; mt < 2; mt++) {
                int row = wm*32 + mt*16 + g;
                const char* p = SAH + row*GPB2 + ks*32 + t4*4;
                ah[mt][0] = *(const uint32_t*)p;
                ah[mt][1] = *(const uint32_t*)(p + 8*GPB2);
                ah[mt][2] = *(const uint32_t*)(p + 16);
                ah[mt][3] = *(const uint32_t*)(p + 8*GPB2 + 16);
                const char* q = SAL + row*GPB2 + ks*32 + t4*4;
                al[mt][0] = *(const uint32_t*)q;
                al[mt][1] = *(const uint32_t*)(q + 8*GPB2);
                al[mt][2] = *(const uint32_t*)(q + 16);
                al[mt][3] = *(const uint32_t*)(q + 8*GPB2 + 16);
            }
            #pragma unroll
            for (int nt = 0; nt < 8; nt++) {
                int brow = wn*64 + nt*8 + g;
                const char* p = SBH + brow*GPB2 + ks*32 + t4*4;
                uint32_t bh0 = *(const uint32_t*)p;
                uint32_t bh1 = *(const uint32_t*)(p + 16);
                const char* q = SBL + brow*GPB2 + ks*32 + t4*4;
                uint32_t bl0 = *(const uint32_t*)q;
                uint32_t bl1 = *(const uint32_t*)(q + 16);
                mma16816(acc[0][nt], ah[0], bh0, bh1);
                mma16816(acc[1][nt], ah[1], bh0, bh1);
                mma16816(acc[0][nt], al[0], bh0, bh1);
                mma16816(acc[1][nt], al[1], bh0, bh1);
                mma16816(acc[0][nt], ah[0], bl0, bl1);
                mma16816(acc[1][nt], ah[1], bl0, bl1);
            }
        }
        __syncthreads();
    }
}

// ---------------------------------------------------------------------------
// Fused QKV projection: z=0 Q(rope+split), z=1 K(rope+split), z=2 V(split)
// ---------------------------------------------------------------------------
__global__ __launch_bounds__(256, 2) void gemm_qkv(const __nv_bfloat16* __restrict__ xh,
                                                const __nv_bfloat16* __restrict__ xl,
                                                const __nv_bfloat16* __restrict__ wh,
                                                const __nv_bfloat16* __restrict__ wl,
                                                __nv_bfloat16* __restrict__ qh,
                                                __nv_bfloat16* __restrict__ ql,
                                                __nv_bfloat16* __restrict__ kh,
                                                __nv_bfloat16* __restrict__ kl,
                                                __nv_bfloat16* __restrict__ vh,
                                                __nv_bfloat16* __restrict__ vl) {
    extern __shared__ char sm[];
    const int z = blockIdx.z;
    const int n0 = blockIdx.x * 128, m0 = blockIdx.y * 128;
    float acc[2][8][4] = {};
    gemm_core(xh, xl, wh + (size_t)z*EMB*EMB, wl + (size_t)z*EMB*EMB,
              sm, smem_u32(sm), m0, n0, acc);

    const int tid = threadIdx.x;
    const int w = tid >> 5, lane = tid & 31, g = lane >> 2, t4 = lane & 3;
    const int wm = w & 3, wn = w >> 2;

    __nv_bfloat16* oh = (z == 0) ? qh : (z == 1) ? kh : vh;
    __nv_bfloat16* ol = (z == 0) ? ql : (z == 1) ? kl : vl;

    if (z < 2) {
        #pragma unroll
        for (int mt = 0; mt < 2; mt++) {
            int rbase = m0 + wm*32 + mt*16 + g;
            #pragma unroll
            for (int jr = 0; jr < 2; jr++) {
                int row = rbase + jr*8;
                int s = row & (SEQ - 1);
                #pragma unroll
                for (int nt = 0; nt < 4; nt++) {
                    int dbase = nt*8 + t4*2;
                    float o0[2], o1[2];
                    #pragma unroll
                    for (int jc = 0; jc < 2; jc++) {
                        int d = dbase + jc;
                        float inv = exp2f(-(float)(2*d) * (13.287712379549449f / 64.0f));
                        float sn, cs;
                        sincosf((float)s * inv, &sn, &cs);
                        float x1 = acc[mt][nt][jr*2+jc];
                        float x2 = acc[mt][nt+4][jr*2+jc];
                        o0[jc] = x1*cs - x2*sn;
                        o1[jc] = x2*cs + x1*sn;
                    }
                    size_t base = (size_t)row * EMB + n0 + wn*64 + dbase;
                    store_split(oh, ol, base,      o0[0], o0[1]);
                    store_split(oh, ol, base + 32, o1[0], o1[1]);
                }
            }
        }
    } else {
        #pragma unroll
        for (int mt = 0; mt < 2; mt++) {
            int row0 = m0 + wm*32 + mt*16 + g;
            #pragma unroll
            for (int nt = 0; nt < 8; nt++) {
                size_t base = (size_t)row0 * EMB + n0 + wn*64 + nt*8 + t4*2;
                store_split(oh, ol, base,          acc[mt][nt][0], acc[mt][nt][1]);
                store_split(oh, ol, base + 8*EMB,  acc[mt][nt][2], acc[mt][nt][3]);
            }
        }
    }
}

// ---------------------------------------------------------------------------
// Output projection
// ---------------------------------------------------------------------------
__global__ __launch_bounds__(256, 2) void gemm_o(const __nv_bfloat16* __restrict__ Ah,
                                              const __nv_bfloat16* __restrict__ Al,
                                              const __nv_bfloat16* __restrict__ Bh,
                                              const __nv_bfloat16* __restrict__ Bl,
                                              float* __restrict__ C) {
    extern __shared__ char sm[];
    const int n0 = blockIdx.x * 128, m0 = blockIdx.y * 128;
    float acc[2][8][4] = {};
    gemm_core(Ah, Al, Bh, Bl, sm, smem_u32(sm), m0, n0, acc);

    const int tid = threadIdx.x;
    const int w = tid >> 5, lane = tid & 31, g = lane >> 2, t4 = lane & 3;
    const int wm = w & 3, wn = w >> 2;
    #pragma unroll
    for (int mt = 0; mt < 2; mt++) {
        int row = m0 + wm*32 + mt*16 + g;
        #pragma unroll
        for (int nt = 0; nt < 8; nt++) {
            float* p0 = C + (size_t)row * EMB + n0 + wn*64 + nt*8 + t4*2;
            *(float2*)p0 = make_float2(acc[mt][nt][0], acc[mt][nt][1]);
            *(float2*)(p0 + 8*EMB) = make_float2(acc[mt][nt][2], acc[mt][nt][3]);
        }
    }
}

// ---------------------------------------------------------------------------
// mma.sync flash attention (R8-proven mainloop), longest CTAs first.
// ---------------------------------------------------------------------------
#define GPB  144
#define AT_TILE  (64*GPB)
#define AT_STAGE (4*AT_TILE)
#define ATTN_SMEM (2*AT_STAGE)

__global__ __launch_bounds__(256) void attn_mma(const __nv_bfloat16* __restrict__ qh,
                                                const __nv_bfloat16* __restrict__ ql,
                                                const __nv_bfloat16* __restrict__ khg,
                                                const __nv_bfloat16* __restrict__ klg,
                                                const __nv_bfloat16* __restrict__ vhg,
                                                const __nv_bfloat16* __restrict__ vlg,
                                                __nv_bfloat16* __restrict__ ch,
                                                __nv_bfloat16* __restrict__ cl) {
    extern __shared__ char sm[];
    const uint32_t smb = smem_u32(sm);

    const int tid = threadIdx.x;
    const int w = tid >> 5, lane = tid & 31, g = lane >> 2, t4 = lane & 3;
    const int qt = gridDim.x - 1 - blockIdx.x;   // longest CTAs first
    const int h = blockIdx.y, b = blockIdx.z;

    const int row_base = qt*128 + w*16;
    const int row0 = row_base + g;
    const int row1 = row0 + 8;
    const size_t hoff = (size_t)h * HDIM;

    uint32_t aqh[4][4], aql[4][4];
    {
        size_t qb = ((size_t)(b*SEQ) + row0) * EMB + hoff;
        #pragma unroll
        for (int ks = 0; ks < 4; ks++) {
            const __nv_bfloat16* p = qh + qb + ks*16 + t4*2;
            aqh[ks][0] = *(const uint32_t*)p;
            aqh[ks][1] = *(const uint32_t*)(p + 8*EMB);
            aqh[ks][2] = *(const uint32_t*)(p + 8);
            aqh[ks][3] = *(const uint32_t*)(p + 8*EMB + 8);
            const __nv_bfloat16* q2 = ql + qb + ks*16 + t4*2;
            aql[ks][0] = *(const uint32_t*)q2;
            aql[ks][1] = *(const uint32_t*)(q2 + 8*EMB);
            aql[ks][2] = *(const uint32_t*)(q2 + 8);
            aql[ks][3] = *(const uint32_t*)(q2 + 8*EMB + 8);
        }
    }

    auto issue = [&](int kt, int stg) {
        size_t kvb = ((size_t)(b*SEQ) + kt*64) * EMB + hoff;
        const char* srcs[4] = { (const char*)(khg + kvb), (const char*)(klg + kvb),
                                (const char*)(vhg + kvb), (const char*)(vlg + kvb) };
        uint32_t dstb = smb + stg * AT_STAGE;
        #pragma unroll
        for (int t = 0; t < 4; t++) {
            #pragma unroll
            for (int j = 0; j < 2; j++) {
                int idx = tid + j*256;
                int r = idx >> 3, c = idx & 7;
                cp16(dstb + t*AT_TILE + r*GPB + c*16, srcs[t] + (size_t)r*2048 + c*16);
            }
        }
        CP_COMMIT();
    };

    float accO[8][4] = {};
    float m0 = -1e30f, m1 = -1e30f, l0 = 0.0f, l1 = 0.0f;
    const float Cs = 0.125f * 1.4426950408889634f;

    const int ntiles = 2*qt + 2;
    const uint32_t vfragoff = (uint32_t)(((lane & 7) + ((lane >> 3) & 1)*8) * GPB + (lane >> 4)*16);

    issue(0, 0);
    for (int kt = 0; kt < ntiles; kt++) {
        int cur = kt & 1;
        if (kt + 1 < ntiles) { issue(kt + 1, cur ^ 1); CP_WAIT1(); }
        else                 { CP_WAIT0(); }
        __syncthreads();

        char* KH = sm + cur*AT_STAGE;
        char* KL = KH + AT_TILE;
        const uint32_t vhb = smb + cur*AT_STAGE + 2*AT_TILE + vfragoff;
        const uint32_t vlb = vhb + AT_TILE;

        if (kt*64 <= row_base + 15) {
            // ---- S = Q K^T (3-pass split) ----
            float s[8][4] = {};
            #pragma unroll
            for (int ks = 0; ks < 4; ks++) {
                #pragma unroll
                for (int nt = 0; nt < 8; nt++) {
                    const char* p = KH + (nt*8+g)*GPB + ks*32 + t4*4;
                    uint32_t bh0 = *(const uint32_t*)p;
                    uint32_t bh1 = *(const uint32_t*)(p + 16);
                    const char* q2 = KL + (nt*8+g)*GPB + ks*32 + t4*4;
                    uint32_t bl0 = *(const uint32_t*)q2;
                    uint32_t bl1 = *(const uint32_t*)(q2 + 16);
                    mma16816(s[nt], aqh[ks], bh0, bh1);
                    mma16816(s[nt], aql[ks], bh0, bh1);
                    mma16816(s[nt], aqh[ks], bl0, bl1);
                }
            }
            // ---- mask + scale ----
            #pragma unroll
            for (int nt = 0; nt < 8; nt++) {
                int colb = kt*64 + nt*8 + t4*2;
                s[nt][0] = (colb     > row0) ? -3e28f : s[nt][0]*Cs;
                s[nt][1] = (colb + 1 > row0) ? -3e28f : s[nt][1]*Cs;
                s[nt][2] = (colb     > row1) ? -3e28f : s[nt][2]*Cs;
                s[nt][3] = (colb + 1 > row1) ? -3e28f : s[nt][3]*Cs;
            }
            // ---- row max ----
            float rm0 = -3e28f, rm1 = -3e28f;
            #pragma unroll
            for (int nt = 0; nt < 8; nt++) {
                rm0 = fmaxf(rm0, fmaxf(s[nt][0], s[nt][1]));
                rm1 = fmaxf(rm1, fmaxf(s[nt][2], s[nt][3]));
            }
            rm0 = fmaxf(rm0, __shfl_xor_sync(0xffffffffu, rm0, 1));
            rm0 = fmaxf(rm0, __shfl_xor_sync(0xffffffffu, rm0, 2));
            rm1 = fmaxf(rm1, __shfl_xor_sync(0xffffffffu, rm1, 1));
            rm1 = fmaxf(rm1, __shfl_xor_sync(0xffffffffu, rm1, 2));

            float mn0 = fmaxf(m0, rm0), mn1 = fmaxf(m1, rm1);
            float alpha0 = exp2f(m0 - mn0), alpha1 = exp2f(m1 - mn1);
            m0 = mn0; m1 = mn1;

            float sum0 = 0.0f, sum1 = 0.0f;
            uint32_t aph[4][4], apl[4][4];
            #pragma unroll
            for (int nt = 0; nt < 8; nt++) {
                float p0 = exp2f(s[nt][0] - m0);
                float p1 = exp2f(s[nt][1] - m0);
                float p2 = exp2f(s[nt][2] - m1);
                float p3 = exp2f(s[nt][3] - m1);
                sum0 += p0 + p1;  sum1 += p2 + p3;
                __nv_bfloat16 h0 = __float2bfloat16_rn(p0), h1b = __float2bfloat16_rn(p1);
                __nv_bfloat16 h2 = __float2bfloat16_rn(p2), h3b = __float2bfloat16_rn(p3);
                float r0 = p0 - __bfloat162float(h0), r1 = p1 - __bfloat162float(h1b);
                float r2 = p2 - __bfloat162float(h2), r3 = p3 - __bfloat162float(h3b);
                int kc = nt >> 1, odd = nt & 1;
                __nv_bfloat162 th01(h0, h1b), th23(h2, h3b);
                aph[kc][odd ? 2 : 0] = *(uint32_t*)&th01;
                aph[kc][odd ? 3 : 1] = *(uint32_t*)&th23;
                apl[kc][odd ? 2 : 0] = packbf(r0, r1);
                apl[kc][odd ? 3 : 1] = packbf(r2, r3);
            }
            sum0 += __shfl_xor_sync(0xffffffffu, sum0, 1);
            sum0 += __shfl_xor_sync(0xffffffffu, sum0, 2);
            sum1 += __shfl_xor_sync(0xffffffffu, sum1, 1);
            sum1 += __shfl_xor_sync(0xffffffffu, sum1, 2);
            l0 = l0 * alpha0 + sum0;
            l1 = l1 * alpha1 + sum1;

            #pragma unroll
            for (int nt = 0; nt < 8; nt++) {
                accO[nt][0] *= alpha0; accO[nt][1] *= alpha0;
                accO[nt][2] *= alpha1; accO[nt][3] *= alpha1;
            }
            // ---- O += P V (3-pass), V via ldmatrix.trans ----
            #pragma unroll
            for (int ks = 0; ks < 4; ks++) {
                #pragma unroll
                for (int ntp = 0; ntp < 4; ntp++) {
                    uint32_t r0, r1, r2, r3;
                    ldsm4t(r0, r1, r2, r3, vhb + ks*16*GPB + ntp*32);
                    mma16816(accO[2*ntp],   aph[ks], r0, r1);
                    mma16816(accO[2*ntp+1], aph[ks], r2, r3);
                    mma16816(accO[2*ntp],   apl[ks], r0, r1);
                    mma16816(accO[2*ntp+1], apl[ks], r2, r3);
                    ldsm4t(r0, r1, r2, r3, vlb + ks*16*GPB + ntp*32);
                    mma16816(accO[2*ntp],   aph[ks], r0, r1);
                    mma16816(accO[2*ntp+1], aph[ks], r2, r3);
                }
            }
        }
        __syncthreads();
    }

    float inv0 = 1.0f / l0, inv1 = 1.0f / l1;
    size_t ob = ((size_t)(b*SEQ) + row0) * EMB + hoff;
    #pragma unroll
    for (int nt = 0; nt < 8; nt++) {
        store_split(ch, cl, ob + nt*8 + t4*2,          accO[nt][0]*inv0, accO[nt][1]*inv0);
        store_split(ch, cl, ob + 8*EMB + nt*8 + t4*2,  accO[nt][2]*inv1, accO[nt][3]*inv1);
    }
}

// ---------------------------------------------------------------------------
extern "C" void kernel_launch(void* const* d_in, const int* in_sizes, int n_in,
                              void* d_out, int out_size) {
    const float* x  = (const float*)d_in[0];
    const float* Wq = (const float*)d_in[1];
    const float* Wk = (const float*)d_in[2];
    const float* Wv = (const float*)d_in[3];
    const float* Wo = (const float*)d_in[4];
    float* out = (float*)d_out;

    __nv_bfloat16 *xh, *xl, *ch, *cl, *wh, *wl;
    __nv_bfloat16 *qhp, *qlp, *khp, *klp, *vhp, *vlp;
    cudaGetSymbolAddress((void**)&xh, g_xh);
    cudaGetSymbolAddress((void**)&xl, g_xl);
    cudaGetSymbolAddress((void**)&ch, g_ch);
    cudaGetSymbolAddress((void**)&cl, g_cl);
    cudaGetSymbolAddress((void**)&wh, g_wh);
    cudaGetSymbolAddress((void**)&wl, g_wl);
    cudaGetSymbolAddress((void**)&qhp, g_qh);
    cudaGetSymbolAddress((void**)&qlp, g_ql);
    cudaGetSymbolAddress((void**)&khp, g_kh);
    cudaGetSymbolAddress((void**)&klp, g_kl);
    cudaGetSymbolAddress((void**)&vhp, g_vh);
    cudaGetSymbolAddress((void**)&vlp, g_vl);

    cudaFuncSetAttribute(gemm_qkv, cudaFuncAttributeMaxDynamicSharedMemorySize, GT_SMEM);
    cudaFuncSetAttribute(gemm_o,   cudaFuncAttributeMaxDynamicSharedMemorySize, GT_SMEM);
    cudaFuncSetAttribute(attn_mma, cudaFuncAttributeMaxDynamicSharedMemorySize, ATTN_SMEM);

    split_all<<<(NX4 + 4*NW4) / 256, 256>>>((const float4*)x,
        (const float4*)Wq, (const float4*)Wk, (const float4*)Wv, (const float4*)Wo,
        (__nv_bfloat162*)xh, (__nv_bfloat162*)xl,
        (__nv_bfloat162*)wh, (__nv_bfloat162*)wl);

    gemm_qkv<<<dim3(EMB/128, NROWS/128, 3), 256, GT_SMEM>>>(
        xh, xl, wh, wl, qhp, qlp, khp, klp, vhp, vlp);

    attn_mma<<<dim3(SEQ/128, HEADS, BATCH), 256, ATTN_SMEM>>>(
        qhp, qlp, khp, klp, vhp, vlp, ch, cl);

    gemm_o<<<dim3(EMB/128, NROWS/128), 256, GT_SMEM>>>(
        ch, cl, wh + 3*(size_t)EMB*EMB, wl + 3*(size_t)EMB*EMB, out);
}

// round 12
// speedup vs baseline: 1.5659x; 1.5659x over previous
#include <cuda_runtime.h>
#include <cuda_bf16.h>
#include <cstdint>
#include <math.h>

#define BATCH 2
#define SEQ   2048
#define EMB   1024
#define HEADS 16
#define HDIM  64
#define NROWS (BATCH*SEQ)

// ---------------- scratch (__device__ globals; no allocs allowed) -----------
__device__ __nv_bfloat16 g_xh[NROWS*EMB], g_xl[NROWS*EMB];
__device__ __nv_bfloat16 g_ch[NROWS*EMB], g_cl[NROWS*EMB];
__device__ __nv_bfloat16 g_wh[4][EMB*EMB], g_wl[4][EMB*EMB];
__device__ __nv_bfloat16 g_qh[NROWS*EMB], g_ql[NROWS*EMB];
__device__ __nv_bfloat16 g_kh[NROWS*EMB], g_kl[NROWS*EMB];
__device__ __nv_bfloat16 g_vh[NROWS*EMB], g_vl[NROWS*EMB];

// ---------------- helpers ----------------------------------------------------
__device__ __forceinline__ uint32_t smem_u32(const void* p) {
    uint32_t a;
    asm("{ .reg .u64 t; cvta.to.shared.u64 t, %1; cvt.u32.u64 %0, t; }" : "=r"(a) : "l"(p));
    return a;
}
__device__ __forceinline__ void mma16816(float* c, const uint32_t* a,
                                         uint32_t b0, uint32_t b1) {
    asm volatile(
        "mma.sync.aligned.m16n8k16.row.col.f32.bf16.bf16.f32 "
        "{%0,%1,%2,%3}, {%4,%5,%6,%7}, {%8,%9}, {%0,%1,%2,%3};"
        : "+f"(c[0]), "+f"(c[1]), "+f"(c[2]), "+f"(c[3])
        : "r"(a[0]), "r"(a[1]), "r"(a[2]), "r"(a[3]), "r"(b0), "r"(b1));
}
__device__ __forceinline__ void ldsm4t(uint32_t& r0, uint32_t& r1,
                                       uint32_t& r2, uint32_t& r3, uint32_t addr) {
    asm volatile("ldmatrix.sync.aligned.m8n8.x4.trans.shared.b16 {%0,%1,%2,%3}, [%4];"
        : "=r"(r0), "=r"(r1), "=r"(r2), "=r"(r3) : "r"(addr));
}
__device__ __forceinline__ void cp16(uint32_t dst, const void* src) {
    asm volatile("cp.async.cg.shared.global [%0], [%1], 16;" :: "r"(dst), "l"(src) : "memory");
}
#define CP_COMMIT() asm volatile("cp.async.commit_group;" ::: "memory")
#define CP_WAIT1()  asm volatile("cp.async.wait_group 1;" ::: "memory")
#define CP_WAIT0()  asm volatile("cp.async.wait_group 0;" ::: "memory")

__device__ __forceinline__ uint32_t packbf(float lo, float hi) {
    __nv_bfloat162 t = __floats2bfloat162_rn(lo, hi);
    return *reinterpret_cast<uint32_t*>(&t);
}
__device__ __forceinline__ void store_split(__nv_bfloat16* oh, __nv_bfloat16* ol,
                                            size_t idx, float v0, float v1) {
    __nv_bfloat16 h0 = __float2bfloat16_rn(v0), h1 = __float2bfloat16_rn(v1);
    *(__nv_bfloat162*)(oh + idx) = __nv_bfloat162(h0, h1);
    *(__nv_bfloat162*)(ol + idx) = __nv_bfloat162(
        __float2bfloat16_rn(v0 - __bfloat162float(h0)),
        __float2bfloat16_rn(v1 - __bfloat162float(h1)));
}

// ---------------------------------------------------------------------------
// fused split: x + 4 weights in ONE launch
// ---------------------------------------------------------------------------
#define NX4 (NROWS*EMB/4)     // 1048576
#define NW4 (EMB*EMB/4)       // 262144 = 2^18

__global__ __launch_bounds__(256) void split_all(const float4* __restrict__ x,
                                                 const float4* __restrict__ w0,
                                                 const float4* __restrict__ w1,
                                                 const float4* __restrict__ w2,
                                                 const float4* __restrict__ w3,
                                                 __nv_bfloat162* __restrict__ xh,
                                                 __nv_bfloat162* __restrict__ xl,
                                                 __nv_bfloat162* __restrict__ wh,
                                                 __nv_bfloat162* __restrict__ wl) {
    int i = blockIdx.x * blockDim.x + threadIdx.x;
    const float4* src; __nv_bfloat162* oh; __nv_bfloat162* ol; int idx;
    if (i < NX4) {
        src = x; oh = xh; ol = xl; idx = i;
    } else {
        int j = i - NX4;
        int wsel = j >> 18;
        idx = j & (NW4 - 1);
        src = (wsel == 0) ? w0 : (wsel == 1) ? w1 : (wsel == 2) ? w2 : w3;
        oh = wh + (size_t)wsel * (EMB*EMB/2);
        ol = wl + (size_t)wsel * (EMB*EMB/2);
    }
    float4 a = src[idx];
    __nv_bfloat16 h0 = __float2bfloat16_rn(a.x);
    __nv_bfloat16 h1 = __float2bfloat16_rn(a.y);
    __nv_bfloat16 h2 = __float2bfloat16_rn(a.z);
    __nv_bfloat16 h3 = __float2bfloat16_rn(a.w);
    oh[idx*2+0] = __nv_bfloat162(h0, h1);
    oh[idx*2+1] = __nv_bfloat162(h2, h3);
    ol[idx*2+0] = __nv_bfloat162(__float2bfloat16_rn(a.x - __bfloat162float(h0)),
                                 __float2bfloat16_rn(a.y - __bfloat162float(h1)));
    ol[idx*2+1] = __nv_bfloat162(__float2bfloat16_rn(a.z - __bfloat162float(h2)),
                                 __float2bfloat16_rn(a.w - __bfloat162float(h3)));
}

// ---------------------------------------------------------------------------
// GEMM core (R8-proven): 128x128 CTA tile, 8 warps (4m x 2n), warp tile 32x64.
// k-chunk 64, cp.async double buffer, scalar LDS frag loads, 3-pass split.
// ---------------------------------------------------------------------------
#define GP   72
#define GPB  144
#define GT_TILE  (128*GPB)          // 18432 B per tile
#define GT_STAGE (4*GT_TILE)        // 73728 B
#define GT_SMEM  (2*GT_STAGE)       // 147456 B

__device__ __forceinline__ void gemm_core(const __nv_bfloat16* __restrict__ Ah,
                                          const __nv_bfloat16* __restrict__ Al,
                                          const __nv_bfloat16* __restrict__ Bh,
                                          const __nv_bfloat16* __restrict__ Bl,
                                          char* sm, uint32_t smb,
                                          int m0, int n0, float acc[2][8][4]) {
    const int tid = threadIdx.x;
    const int w = tid >> 5, lane = tid & 31, g = lane >> 2, t4 = lane & 3;
    const int wm = w & 3, wn = w >> 2;

    const char* gsrc[4] = { (const char*)(Ah + (size_t)m0 * EMB),
                            (const char*)(Al + (size_t)m0 * EMB),
                            (const char*)(Bh + (size_t)n0 * EMB),
                            (const char*)(Bl + (size_t)n0 * EMB) };

    auto issue = [&](int kc, int stg) {
        uint32_t dstb = smb + stg * GT_STAGE;
        #pragma unroll
        for (int mX = 0; mX < 4; mX++) {
            #pragma unroll
            for (int j = 0; j < 4; j++) {
                int idx = tid + j * 256;
                int r = idx >> 3, c = idx & 7;
                cp16(dstb + mX*GT_TILE + r*GPB + c*16,
                     gsrc[mX] + kc*128 + (size_t)r*2048 + c*16);
            }
        }
        CP_COMMIT();
    };

    issue(0, 0);
    for (int kc = 0; kc < 16; kc++) {
        int cur = kc & 1;
        if (kc < 15) { issue(kc + 1, cur ^ 1); CP_WAIT1(); }
        else         { CP_WAIT0(); }
        __syncthreads();

        char* SAH = sm + cur*GT_STAGE;
        char* SAL = SAH + GT_TILE;
        char* SBH = SAH + 2*GT_TILE;
        char* SBL = SAH + 3*GT_TILE;

        #pragma unroll
        for (int ks = 0; ks < 4; ks++) {
            uint32_t ah[2][4], al[2][4];
            #pragma unroll
            for (int mt = 0; mt < 2; mt++) {
                int row = wm*32 + mt*16 + g;
                const char* p = SAH + row*GPB + ks*32 + t4*4;
                ah[mt][0] = *(const uint32_t*)p;
                ah[mt][1] = *(const uint32_t*)(p + 8*GPB);
                ah[mt][2] = *(const uint32_t*)(p + 16);
                ah[mt][3] = *(const uint32_t*)(p + 8*GPB + 16);
                const char* q = SAL + row*GPB + ks*32 + t4*4;
                al[mt][0] = *(const uint32_t*)q;
                al[mt][1] = *(const uint32_t*)(q + 8*GPB);
                al[mt][2] = *(const uint32_t*)(q + 16);
                al[mt][3] = *(const uint32_t*)(q + 8*GPB + 16);
            }
            #pragma unroll
            for (int nt = 0; nt < 8; nt++) {
                int brow = wn*64 + nt*8 + g;
                const char* p = SBH + brow*GPB + ks*32 + t4*4;
                uint32_t bh0 = *(const uint32_t*)p;
                uint32_t bh1 = *(const uint32_t*)(p + 16);
                const char* q = SBL + brow*GPB + ks*32 + t4*4;
                uint32_t bl0 = *(const uint32_t*)q;
                uint32_t bl1 = *(const uint32_t*)(q + 16);
                mma16816(acc[0][nt], ah[0], bh0, bh1);
                mma16816(acc[1][nt], ah[1], bh0, bh1);
                mma16816(acc[0][nt], al[0], bh0, bh1);
                mma16816(acc[1][nt], al[1], bh0, bh1);
                mma16816(acc[0][nt], ah[0], bl0, bl1);
                mma16816(acc[1][nt], ah[1], bl0, bl1);
            }
        }
        __syncthreads();
    }
}

// ---------------------------------------------------------------------------
// Fused QKV projection: z=0 Q(rope+split), z=1 K(rope+split), z=2 V(split)
// ---------------------------------------------------------------------------
__global__ __launch_bounds__(256) void gemm_qkv(const __nv_bfloat16* __restrict__ xh,
                                                const __nv_bfloat16* __restrict__ xl,
                                                const __nv_bfloat16* __restrict__ wh,
                                                const __nv_bfloat16* __restrict__ wl,
                                                __nv_bfloat16* __restrict__ qh,
                                                __nv_bfloat16* __restrict__ ql,
                                                __nv_bfloat16* __restrict__ kh,
                                                __nv_bfloat16* __restrict__ kl,
                                                __nv_bfloat16* __restrict__ vh,
                                                __nv_bfloat16* __restrict__ vl) {
    extern __shared__ char sm[];
    const int z = blockIdx.z;
    const int n0 = blockIdx.x * 128, m0 = blockIdx.y * 128;
    float acc[2][8][4] = {};
    gemm_core(xh, xl, wh + (size_t)z*EMB*EMB, wl + (size_t)z*EMB*EMB,
              sm, smem_u32(sm), m0, n0, acc);

    const int tid = threadIdx.x;
    const int w = tid >> 5, lane = tid & 31, g = lane >> 2, t4 = lane & 3;
    const int wm = w & 3, wn = w >> 2;

    __nv_bfloat16* oh = (z == 0) ? qh : (z == 1) ? kh : vh;
    __nv_bfloat16* ol = (z == 0) ? ql : (z == 1) ? kl : vl;

    if (z < 2) {
        #pragma unroll
        for (int mt = 0; mt < 2; mt++) {
            int rbase = m0 + wm*32 + mt*16 + g;
            #pragma unroll
            for (int jr = 0; jr < 2; jr++) {
                int row = rbase + jr*8;
                int s = row & (SEQ - 1);
                #pragma unroll
                for (int nt = 0; nt < 4; nt++) {
                    int dbase = nt*8 + t4*2;
                    float o0[2], o1[2];
                    #pragma unroll
                    for (int jc = 0; jc < 2; jc++) {
                        int d = dbase + jc;
                        float inv = exp2f(-(float)(2*d) * (13.287712379549449f / 64.0f));
                        float sn, cs;
                        sincosf((float)s * inv, &sn, &cs);
                        float x1 = acc[mt][nt][jr*2+jc];
                        float x2 = acc[mt][nt+4][jr*2+jc];
                        o0[jc] = x1*cs - x2*sn;
                        o1[jc] = x2*cs + x1*sn;
                    }
                    size_t base = (size_t)row * EMB + n0 + wn*64 + dbase;
                    store_split(oh, ol, base,      o0[0], o0[1]);
                    store_split(oh, ol, base + 32, o1[0], o1[1]);
                }
            }
        }
    } else {
        #pragma unroll
        for (int mt = 0; mt < 2; mt++) {
            int row0 = m0 + wm*32 + mt*16 + g;
            #pragma unroll
            for (int nt = 0; nt < 8; nt++) {
                size_t base = (size_t)row0 * EMB + n0 + wn*64 + nt*8 + t4*2;
                store_split(oh, ol, base,          acc[mt][nt][0], acc[mt][nt][1]);
                store_split(oh, ol, base + 8*EMB,  acc[mt][nt][2], acc[mt][nt][3]);
            }
        }
    }
}

// ---------------------------------------------------------------------------
// Output projection
// ---------------------------------------------------------------------------
__global__ __launch_bounds__(256) void gemm_o(const __nv_bfloat16* __restrict__ Ah,
                                              const __nv_bfloat16* __restrict__ Al,
                                              const __nv_bfloat16* __restrict__ Bh,
                                              const __nv_bfloat16* __restrict__ Bl,
                                              float* __restrict__ C) {
    extern __shared__ char sm[];
    const int n0 = blockIdx.x * 128, m0 = blockIdx.y * 128;
    float acc[2][8][4] = {};
    gemm_core(Ah, Al, Bh, Bl, sm, smem_u32(sm), m0, n0, acc);

    const int tid = threadIdx.x;
    const int w = tid >> 5, lane = tid & 31, g = lane >> 2, t4 = lane & 3;
    const int wm = w & 3, wn = w >> 2;
    #pragma unroll
    for (int mt = 0; mt < 2; mt++) {
        int row = m0 + wm*32 + mt*16 + g;
        #pragma unroll
        for (int nt = 0; nt < 8; nt++) {
            float* p0 = C + (size_t)row * EMB + n0 + wn*64 + nt*8 + t4*2;
            *(float2*)p0 = make_float2(acc[mt][nt][0], acc[mt][nt][1]);
            *(float2*)(p0 + 8*EMB) = make_float2(acc[mt][nt][2], acc[mt][nt][3]);
        }
    }
}

// ---------------------------------------------------------------------------
// mma.sync flash attention (R8-proven mainloop), longest CTAs first.
// ---------------------------------------------------------------------------
#define AT_TILE  (64*GPB)
#define AT_STAGE (4*AT_TILE)
#define ATTN_SMEM (2*AT_STAGE)

__global__ __launch_bounds__(256) void attn_mma(const __nv_bfloat16* __restrict__ qh,
                                                const __nv_bfloat16* __restrict__ ql,
                                                const __nv_bfloat16* __restrict__ khg,
                                                const __nv_bfloat16* __restrict__ klg,
                                                const __nv_bfloat16* __restrict__ vhg,
                                                const __nv_bfloat16* __restrict__ vlg,
                                                __nv_bfloat16* __restrict__ ch,
                                                __nv_bfloat16* __restrict__ cl) {
    extern __shared__ char sm[];
    const uint32_t smb = smem_u32(sm);

    const int tid = threadIdx.x;
    const int w = tid >> 5, lane = tid & 31, g = lane >> 2, t4 = lane & 3;
    const int qt = gridDim.x - 1 - blockIdx.x;   // longest CTAs first
    const int h = blockIdx.y, b = blockIdx.z;

    const int row_base = qt*128 + w*16;
    const int row0 = row_base + g;
    const int row1 = row0 + 8;
    const size_t hoff = (size_t)h * HDIM;

    uint32_t aqh[4][4], aql[4][4];
    {
        size_t qb = ((size_t)(b*SEQ) + row0) * EMB + hoff;
        #pragma unroll
        for (int ks = 0; ks < 4; ks++) {
            const __nv_bfloat16* p = qh + qb + ks*16 + t4*2;
            aqh[ks][0] = *(const uint32_t*)p;
            aqh[ks][1] = *(const uint32_t*)(p + 8*EMB);
            aqh[ks][2] = *(const uint32_t*)(p + 8);
            aqh[ks][3] = *(const uint32_t*)(p + 8*EMB + 8);
            const __nv_bfloat16* q2 = ql + qb + ks*16 + t4*2;
            aql[ks][0] = *(const uint32_t*)q2;
            aql[ks][1] = *(const uint32_t*)(q2 + 8*EMB);
            aql[ks][2] = *(const uint32_t*)(q2 + 8);
            aql[ks][3] = *(const uint32_t*)(q2 + 8*EMB + 8);
        }
    }

    auto issue = [&](int kt, int stg) {
        size_t kvb = ((size_t)(b*SEQ) + kt*64) * EMB + hoff;
        const char* srcs[4] = { (const char*)(khg + kvb), (const char*)(klg + kvb),
                                (const char*)(vhg + kvb), (const char*)(vlg + kvb) };
        uint32_t dstb = smb + stg * AT_STAGE;
        #pragma unroll
        for (int t = 0; t < 4; t++) {
            #pragma unroll
            for (int j = 0; j < 2; j++) {
                int idx = tid + j*256;
                int r = idx >> 3, c = idx & 7;
                cp16(dstb + t*AT_TILE + r*GPB + c*16, srcs[t] + (size_t)r*2048 + c*16);
            }
        }
        CP_COMMIT();
    };

    float accO[8][4] = {};
    float m0 = -1e30f, m1 = -1e30f, l0 = 0.0f, l1 = 0.0f;
    const float Cs = 0.125f * 1.4426950408889634f;

    const int ntiles = 2*qt + 2;
    const uint32_t vfragoff = (uint32_t)(((lane & 7) + ((lane >> 3) & 1)*8) * GPB + (lane >> 4)*16);

    issue(0, 0);
    for (int kt = 0; kt < ntiles; kt++) {
        int cur = kt & 1;
        if (kt + 1 < ntiles) { issue(kt + 1, cur ^ 1); CP_WAIT1(); }
        else                 { CP_WAIT0(); }
        __syncthreads();

        char* KH = sm + cur*AT_STAGE;
        char* KL = KH + AT_TILE;
        const uint32_t vhb = smb + cur*AT_STAGE + 2*AT_TILE + vfragoff;
        const uint32_t vlb = vhb + AT_TILE;

        if (kt*64 <= row_base + 15) {
            // ---- S = Q K^T (3-pass split) ----
            float s[8][4] = {};
            #pragma unroll
            for (int ks = 0; ks < 4; ks++) {
                #pragma unroll
                for (int nt = 0; nt < 8; nt++) {
                    const char* p = KH + (nt*8+g)*GPB + ks*32 + t4*4;
                    uint32_t bh0 = *(const uint32_t*)p;
                    uint32_t bh1 = *(const uint32_t*)(p + 16);
                    const char* q2 = KL + (nt*8+g)*GPB + ks*32 + t4*4;
                    uint32_t bl0 = *(const uint32_t*)q2;
                    uint32_t bl1 = *(const uint32_t*)(q2 + 16);
                    mma16816(s[nt], aqh[ks], bh0, bh1);
                    mma16816(s[nt], aql[ks], bh0, bh1);
                    mma16816(s[nt], aqh[ks], bl0, bl1);
                }
            }
            // ---- mask + scale ----
            #pragma unroll
            for (int nt = 0; nt < 8; nt++) {
                int colb = kt*64 + nt*8 + t4*2;
                s[nt][0] = (colb     > row0) ? -3e28f : s[nt][0]*Cs;
                s[nt][1] = (colb + 1 > row0) ? -3e28f : s[nt][1]*Cs;
                s[nt][2] = (colb     > row1) ? -3e28f : s[nt][2]*Cs;
                s[nt][3] = (colb + 1 > row1) ? -3e28f : s[nt][3]*Cs;
            }
            // ---- row max ----
            float rm0 = -3e28f, rm1 = -3e28f;
            #pragma unroll
            for (int nt = 0; nt < 8; nt++) {
                rm0 = fmaxf(rm0, fmaxf(s[nt][0], s[nt][1]));
                rm1 = fmaxf(rm1, fmaxf(s[nt][2], s[nt][3]));
            }
            rm0 = fmaxf(rm0, __shfl_xor_sync(0xffffffffu, rm0, 1));
            rm0 = fmaxf(rm0, __shfl_xor_sync(0xffffffffu, rm0, 2));
            rm1 = fmaxf(rm1, __shfl_xor_sync(0xffffffffu, rm1, 1));
            rm1 = fmaxf(rm1, __shfl_xor_sync(0xffffffffu, rm1, 2));

            float mn0 = fmaxf(m0, rm0), mn1 = fmaxf(m1, rm1);
            float alpha0 = exp2f(m0 - mn0), alpha1 = exp2f(m1 - mn1);
            m0 = mn0; m1 = mn1;

            float sum0 = 0.0f, sum1 = 0.0f;
            uint32_t aph[4][4], apl[4][4];
            #pragma unroll
            for (int nt = 0; nt < 8; nt++) {
                float p0 = exp2f(s[nt][0] - m0);
                float p1 = exp2f(s[nt][1] - m0);
                float p2 = exp2f(s[nt][2] - m1);
                float p3 = exp2f(s[nt][3] - m1);
                sum0 += p0 + p1;  sum1 += p2 + p3;
                __nv_bfloat16 h0 = __float2bfloat16_rn(p0), h1b = __float2bfloat16_rn(p1);
                __nv_bfloat16 h2 = __float2bfloat16_rn(p2), h3b = __float2bfloat16_rn(p3);
                float r0 = p0 - __bfloat162float(h0), r1 = p1 - __bfloat162float(h1b);
                float r2 = p2 - __bfloat162float(h2), r3 = p3 - __bfloat162float(h3b);
                int kc = nt >> 1, odd = nt & 1;
                __nv_bfloat162 th01(h0, h1b), th23(h2, h3b);
                aph[kc][odd ? 2 : 0] = *(uint32_t*)&th01;
                aph[kc][odd ? 3 : 1] = *(uint32_t*)&th23;
                apl[kc][odd ? 2 : 0] = packbf(r0, r1);
                apl[kc][odd ? 3 : 1] = packbf(r2, r3);
            }
            sum0 += __shfl_xor_sync(0xffffffffu, sum0, 1);
            sum0 += __shfl_xor_sync(0xffffffffu, sum0, 2);
            sum1 += __shfl_xor_sync(0xffffffffu, sum1, 1);
            sum1 += __shfl_xor_sync(0xffffffffu, sum1, 2);
            l0 = l0 * alpha0 + sum0;
            l1 = l1 * alpha1 + sum1;

            #pragma unroll
            for (int nt = 0; nt < 8; nt++) {
                accO[nt][0] *= alpha0; accO[nt][1] *= alpha0;
                accO[nt][2] *= alpha1; accO[nt][3] *= alpha1;
            }
            // ---- O += P V (3-pass), V via ldmatrix.trans ----
            #pragma unroll
            for (int ks = 0; ks < 4; ks++) {
                #pragma unroll
                for (int ntp = 0; ntp < 4; ntp++) {
                    uint32_t r0, r1, r2, r3;
                    ldsm4t(r0, r1, r2, r3, vhb + ks*16*GPB + ntp*32);
                    mma16816(accO[2*ntp],   aph[ks], r0, r1);
                    mma16816(accO[2*ntp+1], aph[ks], r2, r3);
                    mma16816(accO[2*ntp],   apl[ks], r0, r1);
                    mma16816(accO[2*ntp+1], apl[ks], r2, r3);
                    ldsm4t(r0, r1, r2, r3, vlb + ks*16*GPB + ntp*32);
                    mma16816(accO[2*ntp],   aph[ks], r0, r1);
                    mma16816(accO[2*ntp+1], aph[ks], r2, r3);
                }
            }
        }
        __syncthreads();
    }

    float inv0 = 1.0f / l0, inv1 = 1.0f / l1;
    size_t ob = ((size_t)(b*SEQ) + row0) * EMB + hoff;
    #pragma unroll
    for (int nt = 0; nt < 8; nt++) {
        store_split(ch, cl, ob + nt*8 + t4*2,          accO[nt][0]*inv0, accO[nt][1]*inv0);
        store_split(ch, cl, ob + 8*EMB + nt*8 + t4*2,  accO[nt][2]*inv1, accO[nt][3]*inv1);
    }
}

// ---------------------------------------------------------------------------
extern "C" void kernel_launch(void* const* d_in, const int* in_sizes, int n_in,
                              void* d_out, int out_size) {
    const float* x  = (const float*)d_in[0];
    const float* Wq = (const float*)d_in[1];
    const float* Wk = (const float*)d_in[2];
    const float* Wv = (const float*)d_in[3];
    const float* Wo = (const float*)d_in[4];
    float* out = (float*)d_out;

    __nv_bfloat16 *xh, *xl, *ch, *cl, *wh, *wl;
    __nv_bfloat16 *qhp, *qlp, *khp, *klp, *vhp, *vlp;
    cudaGetSymbolAddress((void**)&xh, g_xh);
    cudaGetSymbolAddress((void**)&xl, g_xl);
    cudaGetSymbolAddress((void**)&ch, g_ch);
    cudaGetSymbolAddress((void**)&cl, g_cl);
    cudaGetSymbolAddress((void**)&wh, g_wh);
    cudaGetSymbolAddress((void**)&wl, g_wl);
    cudaGetSymbolAddress((void**)&qhp, g_qh);
    cudaGetSymbolAddress((void**)&qlp, g_ql);
    cudaGetSymbolAddress((void**)&khp, g_kh);
    cudaGetSymbolAddress((void**)&klp, g_kl);
    cudaGetSymbolAddress((void**)&vhp, g_vh);
    cudaGetSymbolAddress((void**)&vlp, g_vl);

    cudaFuncSetAttribute(gemm_qkv, cudaFuncAttributeMaxDynamicSharedMemorySize, GT_SMEM);
    cudaFuncSetAttribute(gemm_o,   cudaFuncAttributeMaxDynamicSharedMemorySize, GT_SMEM);
    cudaFuncSetAttribute(attn_mma, cudaFuncAttributeMaxDynamicSharedMemorySize, ATTN_SMEM);

    split_all<<<(NX4 + 4*NW4) / 256, 256>>>((const float4*)x,
        (const float4*)Wq, (const float4*)Wk, (const float4*)Wv, (const float4*)Wo,
        (__nv_bfloat162*)xh, (__nv_bfloat162*)xl,
        (__nv_bfloat162*)wh, (__nv_bfloat162*)wl);

    gemm_qkv<<<dim3(EMB/128, NROWS/128, 3), 256, GT_SMEM>>>(
        xh, xl, wh, wl, qhp, qlp, khp, klp, vhp, vlp);

    attn_mma<<<dim3(SEQ/128, HEADS, BATCH), 256, ATTN_SMEM>>>(
        qhp, qlp, khp, klp, vhp, vlp, ch, cl);

    gemm_o<<<dim3(EMB/128, NROWS/128), 256, GT_SMEM>>>(
        ch, cl, wh + 3*(size_t)EMB*EMB, wl + 3*(size_t)EMB*EMB, out);
}

// round 13
// speedup vs baseline: 1.6060x; 1.0256x over previous
#include <cuda_runtime.h>
#include <cuda_bf16.h>
#include <cstdint>
#include <math.h>

#define BATCH 2
#define SEQ   2048
#define EMB   1024
#define HEADS 16
#define HDIM  64
#define NROWS (BATCH*SEQ)

// ---------------- scratch (__device__ globals; no allocs allowed) -----------
__device__ __nv_bfloat16 g_xh[NROWS*EMB], g_xl[NROWS*EMB];
__device__ __nv_bfloat16 g_ch[NROWS*EMB], g_cl[NROWS*EMB];
__device__ __nv_bfloat16 g_wh[4][EMB*EMB], g_wl[4][EMB*EMB];
__device__ __nv_bfloat16 g_qh[NROWS*EMB], g_ql[NROWS*EMB];
__device__ __nv_bfloat16 g_kh[NROWS*EMB], g_kl[NROWS*EMB];
__device__ __nv_bfloat16 g_vh[NROWS*EMB], g_vl[NROWS*EMB];

// ---------------- helpers ----------------------------------------------------
__device__ __forceinline__ uint32_t smem_u32(const void* p) {
    uint32_t a;
    asm("{ .reg .u64 t; cvta.to.shared.u64 t, %1; cvt.u32.u64 %0, t; }" : "=r"(a) : "l"(p));
    return a;
}
__device__ __forceinline__ void mma16816(float* c, const uint32_t* a,
                                         uint32_t b0, uint32_t b1) {
    asm volatile(
        "mma.sync.aligned.m16n8k16.row.col.f32.bf16.bf16.f32 "
        "{%0,%1,%2,%3}, {%4,%5,%6,%7}, {%8,%9}, {%0,%1,%2,%3};"
        : "+f"(c[0]), "+f"(c[1]), "+f"(c[2]), "+f"(c[3])
        : "r"(a[0]), "r"(a[1]), "r"(a[2]), "r"(a[3]), "r"(b0), "r"(b1));
}
__device__ __forceinline__ void ldsm4t(uint32_t& r0, uint32_t& r1,
                                       uint32_t& r2, uint32_t& r3, uint32_t addr) {
    asm volatile("ldmatrix.sync.aligned.m8n8.x4.trans.shared.b16 {%0,%1,%2,%3}, [%4];"
        : "=r"(r0), "=r"(r1), "=r"(r2), "=r"(r3) : "r"(addr));
}
__device__ __forceinline__ void cp16(uint32_t dst, const void* src) {
    asm volatile("cp.async.cg.shared.global [%0], [%1], 16;" :: "r"(dst), "l"(src) : "memory");
}
#define CP_COMMIT() asm volatile("cp.async.commit_group;" ::: "memory")
#define CP_WAIT1()  asm volatile("cp.async.wait_group 1;" ::: "memory")
#define CP_WAIT0()  asm volatile("cp.async.wait_group 0;" ::: "memory")

__device__ __forceinline__ uint32_t packbf(float lo, float hi) {
    __nv_bfloat162 t = __floats2bfloat162_rn(lo, hi);
    return *reinterpret_cast<uint32_t*>(&t);
}
__device__ __forceinline__ void store_split(__nv_bfloat16* oh, __nv_bfloat16* ol,
                                            size_t idx, float v0, float v1) {
    __nv_bfloat16 h0 = __float2bfloat16_rn(v0), h1 = __float2bfloat16_rn(v1);
    *(__nv_bfloat162*)(oh + idx) = __nv_bfloat162(h0, h1);
    *(__nv_bfloat162*)(ol + idx) = __nv_bfloat162(
        __float2bfloat16_rn(v0 - __bfloat162float(h0)),
        __float2bfloat16_rn(v1 - __bfloat162float(h1)));
}

// ---------------------------------------------------------------------------
// fused split: x + 4 weights in ONE launch
// ---------------------------------------------------------------------------
#define NX4 (NROWS*EMB/4)     // 1048576
#define NW4 (EMB*EMB/4)       // 262144 = 2^18

__global__ __launch_bounds__(256) void split_all(const float4* __restrict__ x,
                                                 const float4* __restrict__ w0,
                                                 const float4* __restrict__ w1,
                                                 const float4* __restrict__ w2,
                                                 const float4* __restrict__ w3,
                                                 __nv_bfloat162* __restrict__ xh,
                                                 __nv_bfloat162* __restrict__ xl,
                                                 __nv_bfloat162* __restrict__ wh,
                                                 __nv_bfloat162* __restrict__ wl) {
    int i = blockIdx.x * blockDim.x + threadIdx.x;
    const float4* src; __nv_bfloat162* oh; __nv_bfloat162* ol; int idx;
    if (i < NX4) {
        src = x; oh = xh; ol = xl; idx = i;
    } else {
        int j = i - NX4;
        int wsel = j >> 18;
        idx = j & (NW4 - 1);
        src = (wsel == 0) ? w0 : (wsel == 1) ? w1 : (wsel == 2) ? w2 : w3;
        oh = wh + (size_t)wsel * (EMB*EMB/2);
        ol = wl + (size_t)wsel * (EMB*EMB/2);
    }
    float4 a = src[idx];
    __nv_bfloat16 h0 = __float2bfloat16_rn(a.x);
    __nv_bfloat16 h1 = __float2bfloat16_rn(a.y);
    __nv_bfloat16 h2 = __float2bfloat16_rn(a.z);
    __nv_bfloat16 h3 = __float2bfloat16_rn(a.w);
    oh[idx*2+0] = __nv_bfloat162(h0, h1);
    oh[idx*2+1] = __nv_bfloat162(h2, h3);
    ol[idx*2+0] = __nv_bfloat162(__float2bfloat16_rn(a.x - __bfloat162float(h0)),
                                 __float2bfloat16_rn(a.y - __bfloat162float(h1)));
    ol[idx*2+1] = __nv_bfloat162(__float2bfloat16_rn(a.z - __bfloat162float(h2)),
                                 __float2bfloat16_rn(a.w - __bfloat162float(h3)));
}

// ---------------------------------------------------------------------------
// GEMM core: 256x128 CTA tile, 512 threads = 16 warps (8m x 2n), warp 32x64.
// k-chunk 64, cp.async double buffer, scalar LDS frag loads, 3-pass split.
// ---------------------------------------------------------------------------
#define GP    72
#define GPB   144
#define A_TILE2 (256*GPB)           // 36864 B
#define B_TILE2 (128*GPB)           // 18432 B
#define OFF_AH  0
#define OFF_AL  A_TILE2
#define OFF_BH  (2*A_TILE2)
#define OFF_BL  (2*A_TILE2 + B_TILE2)
#define GT_STAGE (2*A_TILE2 + 2*B_TILE2)   // 110592 B
#define GT_SMEM  (2*GT_STAGE)              // 221184 B

__device__ __forceinline__ void gemm_core(const __nv_bfloat16* __restrict__ Ah,
                                          const __nv_bfloat16* __restrict__ Al,
                                          const __nv_bfloat16* __restrict__ Bh,
                                          const __nv_bfloat16* __restrict__ Bl,
                                          char* sm, uint32_t smb,
                                          int m0, int n0, float acc[2][8][4]) {
    const int tid = threadIdx.x;
    const int w = tid >> 5, lane = tid & 31, g = lane >> 2, t4 = lane & 3;
    const int wm = w & 7, wn = w >> 3;

    const char* gA[2] = { (const char*)(Ah + (size_t)m0 * EMB),
                          (const char*)(Al + (size_t)m0 * EMB) };
    const char* gB[2] = { (const char*)(Bh + (size_t)n0 * EMB),
                          (const char*)(Bl + (size_t)n0 * EMB) };

    auto issue = [&](int kc, int stg) {
        uint32_t dstb = smb + stg * GT_STAGE;
        #pragma unroll
        for (int mX = 0; mX < 2; mX++) {
            const char* src = gA[mX] + kc * 128;
            #pragma unroll
            for (int j = 0; j < 4; j++) {
                int idx = tid + j * 512;        // 0..2047
                int r = idx >> 3, c = idx & 7;
                cp16(dstb + mX*A_TILE2 + r*GPB + c*16, src + (size_t)r*2048 + c*16);
            }
        }
        #pragma unroll
        for (int mX = 0; mX < 2; mX++) {
            const char* src = gB[mX] + kc * 128;
            #pragma unroll
            for (int j = 0; j < 2; j++) {
                int idx = tid + j * 512;        // 0..1023
                int r = idx >> 3, c = idx & 7;
                cp16(dstb + OFF_BH + mX*B_TILE2 + r*GPB + c*16, src + (size_t)r*2048 + c*16);
            }
        }
        CP_COMMIT();
    };

    issue(0, 0);
    for (int kc = 0; kc < 16; kc++) {
        int cur = kc & 1;
        if (kc < 15) { issue(kc + 1, cur ^ 1); CP_WAIT1(); }
        else         { CP_WAIT0(); }
        __syncthreads();

        char* SAH = sm + cur*GT_STAGE + OFF_AH;
        char* SAL = sm + cur*GT_STAGE + OFF_AL;
        char* SBH = sm + cur*GT_STAGE + OFF_BH;
        char* SBL = sm + cur*GT_STAGE + OFF_BL;

        #pragma unroll
        for (int ks = 0; ks < 4; ks++) {
            uint32_t ah[2][4], al[2][4];
            #pragma unroll
            for (int mt = 0; mt < 2; mt++) {
                int row = wm*32 + mt*16 + g;
                const char* p = SAH + row*GPB + ks*32 + t4*4;
                ah[mt][0] = *(const uint32_t*)p;
                ah[mt][1] = *(const uint32_t*)(p + 8*GPB);
                ah[mt][2] = *(const uint32_t*)(p + 16);
                ah[mt][3] = *(const uint32_t*)(p + 8*GPB + 16);
                const char* q = SAL + row*GPB + ks*32 + t4*4;
                al[mt][0] = *(const uint32_t*)q;
                al[mt][1] = *(const uint32_t*)(q + 8*GPB);
                al[mt][2] = *(const uint32_t*)(q + 16);
                al[mt][3] = *(const uint32_t*)(q + 8*GPB + 16);
            }
            #pragma unroll
            for (int nt = 0; nt < 8; nt++) {
                int brow = wn*64 + nt*8 + g;
                const char* p = SBH + brow*GPB + ks*32 + t4*4;
                uint32_t bh0 = *(const uint32_t*)p;
                uint32_t bh1 = *(const uint32_t*)(p + 16);
                const char* q = SBL + brow*GPB + ks*32 + t4*4;
                uint32_t bl0 = *(const uint32_t*)q;
                uint32_t bl1 = *(const uint32_t*)(q + 16);
                mma16816(acc[0][nt], ah[0], bh0, bh1);
                mma16816(acc[1][nt], ah[1], bh0, bh1);
                mma16816(acc[0][nt], al[0], bh0, bh1);
                mma16816(acc[1][nt], al[1], bh0, bh1);
                mma16816(acc[0][nt], ah[0], bl0, bl1);
                mma16816(acc[1][nt], ah[1], bl0, bl1);
            }
        }
        __syncthreads();
    }
}

// ---------------------------------------------------------------------------
// Fused QKV projection: z=0 Q(rope+split), z=1 K(rope+split), z=2 V(split)
// ---------------------------------------------------------------------------
__global__ __launch_bounds__(512, 1) void gemm_qkv(const __nv_bfloat16* __restrict__ xh,
                                                const __nv_bfloat16* __restrict__ xl,
                                                const __nv_bfloat16* __restrict__ wh,
                                                const __nv_bfloat16* __restrict__ wl,
                                                __nv_bfloat16* __restrict__ qh,
                                                __nv_bfloat16* __restrict__ ql,
                                                __nv_bfloat16* __restrict__ kh,
                                                __nv_bfloat16* __restrict__ kl,
                                                __nv_bfloat16* __restrict__ vh,
                                                __nv_bfloat16* __restrict__ vl) {
    extern __shared__ char sm[];
    const int z = blockIdx.z;
    const int n0 = blockIdx.x * 128, m0 = blockIdx.y * 256;
    float acc[2][8][4] = {};
    gemm_core(xh, xl, wh + (size_t)z*EMB*EMB, wl + (size_t)z*EMB*EMB,
              sm, smem_u32(sm), m0, n0, acc);

    const int tid = threadIdx.x;
    const int w = tid >> 5, lane = tid & 31, g = lane >> 2, t4 = lane & 3;
    const int wm = w & 7, wn = w >> 3;

    __nv_bfloat16* oh = (z == 0) ? qh : (z == 1) ? kh : vh;
    __nv_bfloat16* ol = (z == 0) ? ql : (z == 1) ? kl : vl;

    if (z < 2) {
        #pragma unroll
        for (int mt = 0; mt < 2; mt++) {
            int rbase = m0 + wm*32 + mt*16 + g;
            #pragma unroll
            for (int jr = 0; jr < 2; jr++) {
                int row = rbase + jr*8;
                int s = row & (SEQ - 1);
                #pragma unroll
                for (int nt = 0; nt < 4; nt++) {
                    int dbase = nt*8 + t4*2;
                    float o0[2], o1[2];
                    #pragma unroll
                    for (int jc = 0; jc < 2; jc++) {
                        int d = dbase + jc;
                        float inv = exp2f(-(float)(2*d) * (13.287712379549449f / 64.0f));
                        float sn, cs;
                        sincosf((float)s * inv, &sn, &cs);
                        float x1 = acc[mt][nt][jr*2+jc];
                        float x2 = acc[mt][nt+4][jr*2+jc];
                        o0[jc] = x1*cs - x2*sn;
                        o1[jc] = x2*cs + x1*sn;
                    }
                    size_t base = (size_t)row * EMB + n0 + wn*64 + dbase;
                    store_split(oh, ol, base,      o0[0], o0[1]);
                    store_split(oh, ol, base + 32, o1[0], o1[1]);
                }
            }
        }
    } else {
        #pragma unroll
        for (int mt = 0; mt < 2; mt++) {
            int row0 = m0 + wm*32 + mt*16 + g;
            #pragma unroll
            for (int nt = 0; nt < 8; nt++) {
                size_t base = (size_t)row0 * EMB + n0 + wn*64 + nt*8 + t4*2;
                store_split(oh, ol, base,          acc[mt][nt][0], acc[mt][nt][1]);
                store_split(oh, ol, base + 8*EMB,  acc[mt][nt][2], acc[mt][nt][3]);
            }
        }
    }
}

// ---------------------------------------------------------------------------
// Output projection
// ---------------------------------------------------------------------------
__global__ __launch_bounds__(512, 1) void gemm_o(const __nv_bfloat16* __restrict__ Ah,
                                              const __nv_bfloat16* __restrict__ Al,
                                              const __nv_bfloat16* __restrict__ Bh,
                                              const __nv_bfloat16* __restrict__ Bl,
                                              float* __restrict__ C) {
    extern __shared__ char sm[];
    const int n0 = blockIdx.x * 128, m0 = blockIdx.y * 256;
    float acc[2][8][4] = {};
    gemm_core(Ah, Al, Bh, Bl, sm, smem_u32(sm), m0, n0, acc);

    const int tid = threadIdx.x;
    const int w = tid >> 5, lane = tid & 31, g = lane >> 2, t4 = lane & 3;
    const int wm = w & 7, wn = w >> 3;
    #pragma unroll
    for (int mt = 0; mt < 2; mt++) {
        int row = m0 + wm*32 + mt*16 + g;
        #pragma unroll
        for (int nt = 0; nt < 8; nt++) {
            float* p0 = C + (size_t)row * EMB + n0 + wn*64 + nt*8 + t4*2;
            *(float2*)p0 = make_float2(acc[mt][nt][0], acc[mt][nt][1]);
            *(float2*)(p0 + 8*EMB) = make_float2(acc[mt][nt][2], acc[mt][nt][3]);
        }
    }
}

// ---------------------------------------------------------------------------
// mma.sync flash attention (R8-proven mainloop), longest CTAs first.
// ---------------------------------------------------------------------------
#define AT_TILE  (64*GPB)
#define AT_STAGE (4*AT_TILE)
#define ATTN_SMEM (2*AT_STAGE)

__global__ __launch_bounds__(256) void attn_mma(const __nv_bfloat16* __restrict__ qh,
                                                const __nv_bfloat16* __restrict__ ql,
                                                const __nv_bfloat16* __restrict__ khg,
                                                const __nv_bfloat16* __restrict__ klg,
                                                const __nv_bfloat16* __restrict__ vhg,
                                                const __nv_bfloat16* __restrict__ vlg,
                                                __nv_bfloat16* __restrict__ ch,
                                                __nv_bfloat16* __restrict__ cl) {
    extern __shared__ char sm[];
    const uint32_t smb = smem_u32(sm);

    const int tid = threadIdx.x;
    const int w = tid >> 5, lane = tid & 31, g = lane >> 2, t4 = lane & 3;
    const int qt = gridDim.x - 1 - blockIdx.x;   // longest CTAs first
    const int h = blockIdx.y, b = blockIdx.z;

    const int row_base = qt*128 + w*16;
    const int row0 = row_base + g;
    const int row1 = row0 + 8;
    const size_t hoff = (size_t)h * HDIM;

    uint32_t aqh[4][4], aql[4][4];
    {
        size_t qb = ((size_t)(b*SEQ) + row0) * EMB + hoff;
        #pragma unroll
        for (int ks = 0; ks < 4; ks++) {
            const __nv_bfloat16* p = qh + qb + ks*16 + t4*2;
            aqh[ks][0] = *(const uint32_t*)p;
            aqh[ks][1] = *(const uint32_t*)(p + 8*EMB);
            aqh[ks][2] = *(const uint32_t*)(p + 8);
            aqh[ks][3] = *(const uint32_t*)(p + 8*EMB + 8);
            const __nv_bfloat16* q2 = ql + qb + ks*16 + t4*2;
            aql[ks][0] = *(const uint32_t*)q2;
            aql[ks][1] = *(const uint32_t*)(q2 + 8*EMB);
            aql[ks][2] = *(const uint32_t*)(q2 + 8);
            aql[ks][3] = *(const uint32_t*)(q2 + 8*EMB + 8);
        }
    }

    auto issue = [&](int kt, int stg) {
        size_t kvb = ((size_t)(b*SEQ) + kt*64) * EMB + hoff;
        const char* srcs[4] = { (const char*)(khg + kvb), (const char*)(klg + kvb),
                                (const char*)(vhg + kvb), (const char*)(vlg + kvb) };
        uint32_t dstb = smb + stg * AT_STAGE;
        #pragma unroll
        for (int t = 0; t < 4; t++) {
            #pragma unroll
            for (int j = 0; j < 2; j++) {
                int idx = tid + j*256;
                int r = idx >> 3, c = idx & 7;
                cp16(dstb + t*AT_TILE + r*GPB + c*16, srcs[t] + (size_t)r*2048 + c*16);
            }
        }
        CP_COMMIT();
    };

    float accO[8][4] = {};
    float m0 = -1e30f, m1 = -1e30f, l0 = 0.0f, l1 = 0.0f;
    const float Cs = 0.125f * 1.4426950408889634f;

    const int ntiles = 2*qt + 2;
    const uint32_t vfragoff = (uint32_t)(((lane & 7) + ((lane >> 3) & 1)*8) * GPB + (lane >> 4)*16);

    issue(0, 0);
    for (int kt = 0; kt < ntiles; kt++) {
        int cur = kt & 1;
        if (kt + 1 < ntiles) { issue(kt + 1, cur ^ 1); CP_WAIT1(); }
        else                 { CP_WAIT0(); }
        __syncthreads();

        char* KH = sm + cur*AT_STAGE;
        char* KL = KH + AT_TILE;
        const uint32_t vhb = smb + cur*AT_STAGE + 2*AT_TILE + vfragoff;
        const uint32_t vlb = vhb + AT_TILE;

        if (kt*64 <= row_base + 15) {
            // ---- S = Q K^T (3-pass split) ----
            float s[8][4] = {};
            #pragma unroll
            for (int ks = 0; ks < 4; ks++) {
                #pragma unroll
                for (int nt = 0; nt < 8; nt++) {
                    const char* p = KH + (nt*8+g)*GPB + ks*32 + t4*4;
                    uint32_t bh0 = *(const uint32_t*)p;
                    uint32_t bh1 = *(const uint32_t*)(p + 16);
                    const char* q2 = KL + (nt*8+g)*GPB + ks*32 + t4*4;
                    uint32_t bl0 = *(const uint32_t*)q2;
                    uint32_t bl1 = *(const uint32_t*)(q2 + 16);
                    mma16816(s[nt], aqh[ks], bh0, bh1);
                    mma16816(s[nt], aql[ks], bh0, bh1);
                    mma16816(s[nt], aqh[ks], bl0, bl1);
                }
            }
            // ---- mask + scale ----
            #pragma unroll
            for (int nt = 0; nt < 8; nt++) {
                int colb = kt*64 + nt*8 + t4*2;
                s[nt][0] = (colb     > row0) ? -3e28f : s[nt][0]*Cs;
                s[nt][1] = (colb + 1 > row0) ? -3e28f : s[nt][1]*Cs;
                s[nt][2] = (colb     > row1) ? -3e28f : s[nt][2]*Cs;
                s[nt][3] = (colb + 1 > row1) ? -3e28f : s[nt][3]*Cs;
            }
            // ---- row max ----
            float rm0 = -3e28f, rm1 = -3e28f;
            #pragma unroll
            for (int nt = 0; nt < 8; nt++) {
                rm0 = fmaxf(rm0, fmaxf(s[nt][0], s[nt][1]));
                rm1 = fmaxf(rm1, fmaxf(s[nt][2], s[nt][3]));
            }
            rm0 = fmaxf(rm0, __shfl_xor_sync(0xffffffffu, rm0, 1));
            rm0 = fmaxf(rm0, __shfl_xor_sync(0xffffffffu, rm0, 2));
            rm1 = fmaxf(rm1, __shfl_xor_sync(0xffffffffu, rm1, 1));
            rm1 = fmaxf(rm1, __shfl_xor_sync(0xffffffffu, rm1, 2));

            float mn0 = fmaxf(m0, rm0), mn1 = fmaxf(m1, rm1);
            float alpha0 = exp2f(m0 - mn0), alpha1 = exp2f(m1 - mn1);
            m0 = mn0; m1 = mn1;

            float sum0 = 0.0f, sum1 = 0.0f;
            uint32_t aph[4][4], apl[4][4];
            #pragma unroll
            for (int nt = 0; nt < 8; nt++) {
                float p0 = exp2f(s[nt][0] - m0);
                float p1 = exp2f(s[nt][1] - m0);
                float p2 = exp2f(s[nt][2] - m1);
                float p3 = exp2f(s[nt][3] - m1);
                sum0 += p0 + p1;  sum1 += p2 + p3;
                __nv_bfloat16 h0 = __float2bfloat16_rn(p0), h1b = __float2bfloat16_rn(p1);
                __nv_bfloat16 h2 = __float2bfloat16_rn(p2), h3b = __float2bfloat16_rn(p3);
                float r0 = p0 - __bfloat162float(h0), r1 = p1 - __bfloat162float(h1b);
                float r2 = p2 - __bfloat162float(h2), r3 = p3 - __bfloat162float(h3b);
                int kc = nt >> 1, odd = nt & 1;
                __nv_bfloat162 th01(h0, h1b), th23(h2, h3b);
                aph[kc][odd ? 2 : 0] = *(uint32_t*)&th01;
                aph[kc][odd ? 3 : 1] = *(uint32_t*)&th23;
                apl[kc][odd ? 2 : 0] = packbf(r0, r1);
                apl[kc][odd ? 3 : 1] = packbf(r2, r3);
            }
            sum0 += __shfl_xor_sync(0xffffffffu, sum0, 1);
            sum0 += __shfl_xor_sync(0xffffffffu, sum0, 2);
            sum1 += __shfl_xor_sync(0xffffffffu, sum1, 1);
            sum1 += __shfl_xor_sync(0xffffffffu, sum1, 2);
            l0 = l0 * alpha0 + sum0;
            l1 = l1 * alpha1 + sum1;

            #pragma unroll
            for (int nt = 0; nt < 8; nt++) {
                accO[nt][0] *= alpha0; accO[nt][1] *= alpha0;
                accO[nt][2] *= alpha1; accO[nt][3] *= alpha1;
            }
            // ---- O += P V (3-pass), V via ldmatrix.trans ----
            #pragma unroll
            for (int ks = 0; ks < 4; ks++) {
                #pragma unroll
                for (int ntp = 0; ntp < 4; ntp++) {
                    uint32_t r0, r1, r2, r3;
                    ldsm4t(r0, r1, r2, r3, vhb + ks*16*GPB + ntp*32);
                    mma16816(accO[2*ntp],   aph[ks], r0, r1);
                    mma16816(accO[2*ntp+1], aph[ks], r2, r3);
                    mma16816(accO[2*ntp],   apl[ks], r0, r1);
                    mma16816(accO[2*ntp+1], apl[ks], r2, r3);
                    ldsm4t(r0, r1, r2, r3, vlb + ks*16*GPB + ntp*32);
                    mma16816(accO[2*ntp],   aph[ks], r0, r1);
                    mma16816(accO[2*ntp+1], aph[ks], r2, r3);
                }
            }
        }
        __syncthreads();
    }

    float inv0 = 1.0f / l0, inv1 = 1.0f / l1;
    size_t ob = ((size_t)(b*SEQ) + row0) * EMB + hoff;
    #pragma unroll
    for (int nt = 0; nt < 8; nt++) {
        store_split(ch, cl, ob + nt*8 + t4*2,          accO[nt][0]*inv0, accO[nt][1]*inv0);
        store_split(ch, cl, ob + 8*EMB + nt*8 + t4*2,  accO[nt][2]*inv1, accO[nt][3]*inv1);
    }
}

// ---------------------------------------------------------------------------
extern "C" void kernel_launch(void* const* d_in, const int* in_sizes, int n_in,
                              void* d_out, int out_size) {
    const float* x  = (const float*)d_in[0];
    const float* Wq = (const float*)d_in[1];
    const float* Wk = (const float*)d_in[2];
    const float* Wv = (const float*)d_in[3];
    const float* Wo = (const float*)d_in[4];
    float* out = (float*)d_out;

    __nv_bfloat16 *xh, *xl, *ch, *cl, *wh, *wl;
    __nv_bfloat16 *qhp, *qlp, *khp, *klp, *vhp, *vlp;
    cudaGetSymbolAddress((void**)&xh, g_xh);
    cudaGetSymbolAddress((void**)&xl, g_xl);
    cudaGetSymbolAddress((void**)&ch, g_ch);
    cudaGetSymbolAddress((void**)&cl, g_cl);
    cudaGetSymbolAddress((void**)&wh, g_wh);
    cudaGetSymbolAddress((void**)&wl, g_wl);
    cudaGetSymbolAddress((void**)&qhp, g_qh);
    cudaGetSymbolAddress((void**)&qlp, g_ql);
    cudaGetSymbolAddress((void**)&khp, g_kh);
    cudaGetSymbolAddress((void**)&klp, g_kl);
    cudaGetSymbolAddress((void**)&vhp, g_vh);
    cudaGetSymbolAddress((void**)&vlp, g_vl);

    cudaFuncSetAttribute(gemm_qkv, cudaFuncAttributeMaxDynamicSharedMemorySize, GT_SMEM);
    cudaFuncSetAttribute(gemm_o,   cudaFuncAttributeMaxDynamicSharedMemorySize, GT_SMEM);
    cudaFuncSetAttribute(attn_mma, cudaFuncAttributeMaxDynamicSharedMemorySize, ATTN_SMEM);

    split_all<<<(NX4 + 4*NW4) / 256, 256>>>((const float4*)x,
        (const float4*)Wq, (const float4*)Wk, (const float4*)Wv, (const float4*)Wo,
        (__nv_bfloat162*)xh, (__nv_bfloat162*)xl,
        (__nv_bfloat162*)wh, (__nv_bfloat162*)wl);

    gemm_qkv<<<dim3(EMB/128, NROWS/256, 3), 512, GT_SMEM>>>(
        xh, xl, wh, wl, qhp, qlp, khp, klp, vhp, vlp);

    attn_mma<<<dim3(SEQ/128, HEADS, BATCH), 256, ATTN_SMEM>>>(
        qhp, qlp, khp, klp, vhp, vlp, ch, cl);

    gemm_o<<<dim3(EMB/128, NROWS/256), 512, GT_SMEM>>>(
        ch, cl, wh + 3*(size_t)EMB*EMB, wl + 3*(size_t)EMB*EMB, out);
}

// round 15
// speedup vs baseline: 2.2361x; 1.3924x over previous
#include <cuda_runtime.h>
#include <cuda_fp16.h>
#include <cstdint>
#include <math.h>

#define BATCH 2
#define SEQ   2048
#define EMB   1024
#define HEADS 16
#define HDIM  64
#define NROWS (BATCH*SEQ)

// ---------------- scratch (__device__ globals; no allocs allowed) -----------
__device__ __half g_xh[NROWS*EMB], g_xl[NROWS*EMB];
__device__ __half g_ch[NROWS*EMB], g_cl[NROWS*EMB];
__device__ __half g_wh[4][EMB*EMB];
__device__ __half g_qh[NROWS*EMB], g_ql[NROWS*EMB];
__device__ __half g_kh[NROWS*EMB];
__device__ __half g_vh[NROWS*EMB];

// ---------------- helpers ----------------------------------------------------
__device__ __forceinline__ uint32_t smem_u32(const void* p) {
    uint32_t a;
    asm("{ .reg .u64 t; cvta.to.shared.u64 t, %1; cvt.u32.u64 %0, t; }" : "=r"(a) : "l"(p));
    return a;
}
__device__ __forceinline__ void mma16816(float* c, const uint32_t* a,
                                         uint32_t b0, uint32_t b1) {
    asm volatile(
        "mma.sync.aligned.m16n8k16.row.col.f32.f16.f16.f32 "
        "{%0,%1,%2,%3}, {%4,%5,%6,%7}, {%8,%9}, {%0,%1,%2,%3};"
        : "+f"(c[0]), "+f"(c[1]), "+f"(c[2]), "+f"(c[3])
        : "r"(a[0]), "r"(a[1]), "r"(a[2]), "r"(a[3]), "r"(b0), "r"(b1));
}
__device__ __forceinline__ void ldsm4t(uint32_t& r0, uint32_t& r1,
                                       uint32_t& r2, uint32_t& r3, uint32_t addr) {
    asm volatile("ldmatrix.sync.aligned.m8n8.x4.trans.shared.b16 {%0,%1,%2,%3}, [%4];"
        : "=r"(r0), "=r"(r1), "=r"(r2), "=r"(r3) : "r"(addr));
}
__device__ __forceinline__ void cp16(uint32_t dst, const void* src) {
    asm volatile("cp.async.cg.shared.global [%0], [%1], 16;" :: "r"(dst), "l"(src) : "memory");
}
#define CP_COMMIT() asm volatile("cp.async.commit_group;" ::: "memory")
#define CP_WAIT1()  asm volatile("cp.async.wait_group 1;" ::: "memory")
#define CP_WAIT0()  asm volatile("cp.async.wait_group 0;" ::: "memory")

__device__ __forceinline__ uint32_t pack2h(__half a, __half b) {
    __half2 t(a, b);
    return *reinterpret_cast<uint32_t*>(&t);
}
__device__ __forceinline__ uint32_t packh(float a, float b) {
    __half2 t = __floats2half2_rn(a, b);
    return *reinterpret_cast<uint32_t*>(&t);
}
__device__ __forceinline__ void store_split_h(__half* oh, __half* ol,
                                              size_t idx, float v0, float v1) {
    __half h0 = __float2half_rn(v0), h1 = __float2half_rn(v1);
    *(__half2*)(oh + idx) = __half2(h0, h1);
    *(__half2*)(ol + idx) = __half2(
        __float2half_rn(v0 - __half2float(h0)),
        __float2half_rn(v1 - __half2float(h1)));
}
__device__ __forceinline__ void store_h(__half* oh, size_t idx, float v0, float v1) {
    *(__half2*)(oh + idx) = __floats2half2_rn(v0, v1);
}

// ---------------------------------------------------------------------------
// fused split: x (hi+lo fp16) + 4 weights (hi fp16 only) in ONE launch
// ---------------------------------------------------------------------------
#define NX4 (NROWS*EMB/4)     // 1048576
#define NW4 (EMB*EMB/4)       // 262144 = 2^18

__global__ __launch_bounds__(256) void split_all(const float4* __restrict__ x,
                                                 const float4* __restrict__ w0,
                                                 const float4* __restrict__ w1,
                                                 const float4* __restrict__ w2,
                                                 const float4* __restrict__ w3,
                                                 __half2* __restrict__ xh,
                                                 __half2* __restrict__ xl,
                                                 __half2* __restrict__ wh) {
    int i = blockIdx.x * blockDim.x + threadIdx.x;
    if (i < NX4) {
        float4 a = x[i];
        __half h0 = __float2half_rn(a.x), h1 = __float2half_rn(a.y);
        __half h2 = __float2half_rn(a.z), h3 = __float2half_rn(a.w);
        xh[i*2+0] = __half2(h0, h1);
        xh[i*2+1] = __half2(h2, h3);
        xl[i*2+0] = __half2(__float2half_rn(a.x - __half2float(h0)),
                            __float2half_rn(a.y - __half2float(h1)));
        xl[i*2+1] = __half2(__float2half_rn(a.z - __half2float(h2)),
                            __float2half_rn(a.w - __half2float(h3)));
    } else {
        int j = i - NX4;
        int wsel = j >> 18;
        int idx = j & (NW4 - 1);
        const float4* src = (wsel == 0) ? w0 : (wsel == 1) ? w1 : (wsel == 2) ? w2 : w3;
        __half2* oh = wh + (size_t)wsel * (EMB*EMB/2);
        float4 a = src[idx];
        oh[idx*2+0] = __floats2half2_rn(a.x, a.y);
        oh[idx*2+1] = __floats2half2_rn(a.z, a.w);
    }
}

// ---------------------------------------------------------------------------
// GEMM core: 256x128 CTA tile, 512 threads = 16 warps (8m x 2n), warp 32x64.
// fp16 2-pass: C = (Ah+Al)@Bh. k-chunk 64, cp.async double buffer.
// ---------------------------------------------------------------------------
#define GP    72
#define GPB   144
#define A_TILE2 (256*GPB)           // 36864 B
#define B_TILE2 (128*GPB)           // 18432 B
#define OFF_AH  0
#define OFF_AL  A_TILE2
#define OFF_BH  (2*A_TILE2)
#define GT_STAGE (2*A_TILE2 + B_TILE2)   // 92160 B
#define GT_SMEM  (2*GT_STAGE)            // 184320 B

__device__ __forceinline__ void gemm_core(const __half* __restrict__ Ah,
                                          const __half* __restrict__ Al,
                                          const __half* __restrict__ Bh,
                                          char* sm, uint32_t smb,
                                          int m0, int n0, float acc[2][8][4]) {
    const int tid = threadIdx.x;
    const int w = tid >> 5, lane = tid & 31, g = lane >> 2, t4 = lane & 3;
    const int wm = w & 7, wn = w >> 3;

    const char* gA[2] = { (const char*)(Ah + (size_t)m0 * EMB),
                          (const char*)(Al + (size_t)m0 * EMB) };
    const char* gB = (const char*)(Bh + (size_t)n0 * EMB);

    auto issue = [&](int kc, int stg) {
        uint32_t dstb = smb + stg * GT_STAGE;
        #pragma unroll
        for (int mX = 0; mX < 2; mX++) {
            const char* src = gA[mX] + kc * 128;
            #pragma unroll
            for (int j = 0; j < 4; j++) {
                int idx = tid + j * 512;        // 0..2047
                int r = idx >> 3, c = idx & 7;
                cp16(dstb + mX*A_TILE2 + r*GPB + c*16, src + (size_t)r*2048 + c*16);
            }
        }
        {
            const char* src = gB + kc * 128;
            #pragma unroll
            for (int j = 0; j < 2; j++) {
                int idx = tid + j * 512;        // 0..1023
                int r = idx >> 3, c = idx & 7;
                cp16(dstb + OFF_BH + r*GPB + c*16, src + (size_t)r*2048 + c*16);
            }
        }
        CP_COMMIT();
    };

    issue(0, 0);
    for (int kc = 0; kc < 16; kc++) {
        int cur = kc & 1;
        if (kc < 15) { issue(kc + 1, cur ^ 1); CP_WAIT1(); }
        else         { CP_WAIT0(); }
        __syncthreads();

        char* SAH = sm + cur*GT_STAGE + OFF_AH;
        char* SAL = sm + cur*GT_STAGE + OFF_AL;
        char* SBH = sm + cur*GT_STAGE + OFF_BH;

        #pragma unroll
        for (int ks = 0; ks < 4; ks++) {
            uint32_t ah[2][4], al[2][4];
            #pragma unroll
            for (int mt = 0; mt < 2; mt++) {
                int row = wm*32 + mt*16 + g;
                const char* p = SAH + row*GPB + ks*32 + t4*4;
                ah[mt][0] = *(const uint32_t*)p;
                ah[mt][1] = *(const uint32_t*)(p + 8*GPB);
                ah[mt][2] = *(const uint32_t*)(p + 16);
                ah[mt][3] = *(const uint32_t*)(p + 8*GPB + 16);
                const char* q = SAL + row*GPB + ks*32 + t4*4;
                al[mt][0] = *(const uint32_t*)q;
                al[mt][1] = *(const uint32_t*)(q + 8*GPB);
                al[mt][2] = *(const uint32_t*)(q + 16);
                al[mt][3] = *(const uint32_t*)(q + 8*GPB + 16);
            }
            #pragma unroll
            for (int nt = 0; nt < 8; nt++) {
                int brow = wn*64 + nt*8 + g;
                const char* p = SBH + brow*GPB + ks*32 + t4*4;
                uint32_t bh0 = *(const uint32_t*)p;
                uint32_t bh1 = *(const uint32_t*)(p + 16);
                mma16816(acc[0][nt], ah[0], bh0, bh1);
                mma16816(acc[1][nt], ah[1], bh0, bh1);
                mma16816(acc[0][nt], al[0], bh0, bh1);
                mma16816(acc[1][nt], al[1], bh0, bh1);
            }
        }
        __syncthreads();
    }
}

// ---------------------------------------------------------------------------
// Fused QKV: z=0 Q(rope, hi+lo), z=1 K(rope, hi only), z=2 V(hi only)
// ---------------------------------------------------------------------------
__global__ __launch_bounds__(512, 1) void gemm_qkv(const __half* __restrict__ xh,
                                                const __half* __restrict__ xl,
                                                const __half* __restrict__ wh,
                                                __half* __restrict__ qh,
                                                __half* __restrict__ ql,
                                                __half* __restrict__ kh,
                                                __half* __restrict__ vh) {
    extern __shared__ char sm[];
    const int z = blockIdx.z;
    const int n0 = blockIdx.x * 128, m0 = blockIdx.y * 256;
    float acc[2][8][4] = {};
    gemm_core(xh, xl, wh + (size_t)z*EMB*EMB, sm, smem_u32(sm), m0, n0, acc);

    const int tid = threadIdx.x;
    const int w = tid >> 5, lane = tid & 31, g = lane >> 2, t4 = lane & 3;
    const int wm = w & 7, wn = w >> 3;

    if (z < 2) {
        #pragma unroll
        for (int mt = 0; mt < 2; mt++) {
            int rbase = m0 + wm*32 + mt*16 + g;
            #pragma unroll
            for (int jr = 0; jr < 2; jr++) {
                int row = rbase + jr*8;
                int s = row & (SEQ - 1);
                #pragma unroll
                for (int nt = 0; nt < 4; nt++) {
                    int dbase = nt*8 + t4*2;
                    float o0[2], o1[2];
                    #pragma unroll
                    for (int jc = 0; jc < 2; jc++) {
                        int d = dbase + jc;
                        float inv = exp2f(-(float)(2*d) * (13.287712379549449f / 64.0f));
                        float sn, cs;
                        sincosf((float)s * inv, &sn, &cs);
                        float x1 = acc[mt][nt][jr*2+jc];
                        float x2 = acc[mt][nt+4][jr*2+jc];
                        o0[jc] = x1*cs - x2*sn;
                        o1[jc] = x2*cs + x1*sn;
                    }
                    size_t base = (size_t)row * EMB + n0 + wn*64 + dbase;
                    if (z == 0) {
                        store_split_h(qh, ql, base,      o0[0], o0[1]);
                        store_split_h(qh, ql, base + 32, o1[0], o1[1]);
                    } else {
                        store_h(kh, base,      o0[0], o0[1]);
                        store_h(kh, base + 32, o1[0], o1[1]);
                    }
                }
            }
        }
    } else {
        #pragma unroll
        for (int mt = 0; mt < 2; mt++) {
            int row0 = m0 + wm*32 + mt*16 + g;
            #pragma unroll
            for (int nt = 0; nt < 8; nt++) {
                size_t base = (size_t)row0 * EMB + n0 + wn*64 + nt*8 + t4*2;
                store_h(vh, base,         acc[0][nt][0], acc[0][nt][1]);
                store_h(vh, base + 8*EMB, acc[0][nt][2], acc[0][nt][3]);
                size_t base1 = base + 16*EMB;   // mt=1 handled below
                (void)base1;
            }
        }
        // mt=1 rows
        #pragma unroll
        for (int nt = 0; nt < 8; nt++) {
            int row1 = m0 + wm*32 + 16 + g;
            size_t base = (size_t)row1 * EMB + n0 + wn*64 + nt*8 + t4*2;
            store_h(vh, base,         acc[1][nt][0], acc[1][nt][1]);
            store_h(vh, base + 8*EMB, acc[1][nt][2], acc[1][nt][3]);
        }
    }
}

// ---------------------------------------------------------------------------
// Output projection: (ch+cl)@Woh -> fp32 out
// ---------------------------------------------------------------------------
__global__ __launch_bounds__(512, 1) void gemm_o(const __half* __restrict__ Ah,
                                              const __half* __restrict__ Al,
                                              const __half* __restrict__ Bh,
                                              float* __restrict__ C) {
    extern __shared__ char sm[];
    const int n0 = blockIdx.x * 128, m0 = blockIdx.y * 256;
    float acc[2][8][4] = {};
    gemm_core(Ah, Al, Bh, sm, smem_u32(sm), m0, n0, acc);

    const int tid = threadIdx.x;
    const int w = tid >> 5, lane = tid & 31, g = lane >> 2, t4 = lane & 3;
    const int wm = w & 7, wn = w >> 3;
    #pragma unroll
    for (int mt = 0; mt < 2; mt++) {
        int row = m0 + wm*32 + mt*16 + g;
        #pragma unroll
        for (int nt = 0; nt < 8; nt++) {
            float* p0 = C + (size_t)row * EMB + n0 + wn*64 + nt*8 + t4*2;
            *(float2*)p0 = make_float2(acc[mt][nt][0], acc[mt][nt][1]);
            *(float2*)(p0 + 8*EMB) = make_float2(acc[mt][nt][2], acc[mt][nt][3]);
        }
    }
}

// ---------------------------------------------------------------------------
// fp16 flash attention: S=(Qh+Ql)K^T, O=(Ph+Pl)V. K,V unsplit.
// Stage: KH | VH (64x144B each). Double buffered. Longest CTAs first.
// ---------------------------------------------------------------------------
#define AT_TILE  (64*GPB)           // 9216
#define AT_STAGE (2*AT_TILE)        // 18432
#define ATTN_SMEM (2*AT_STAGE)      // 36864

__global__ __launch_bounds__(256) void attn_mma(const __half* __restrict__ qh,
                                                const __half* __restrict__ ql,
                                                const __half* __restrict__ khg,
                                                const __half* __restrict__ vhg,
                                                __half* __restrict__ ch,
                                                __half* __restrict__ cl) {
    extern __shared__ char sm[];
    const uint32_t smb = smem_u32(sm);

    const int tid = threadIdx.x;
    const int w = tid >> 5, lane = tid & 31, g = lane >> 2, t4 = lane & 3;
    const int qt = gridDim.x - 1 - blockIdx.x;   // longest CTAs first
    const int h = blockIdx.y, b = blockIdx.z;

    const int row_base = qt*128 + w*16;
    const int row0 = row_base + g;
    const int row1 = row0 + 8;
    const size_t hoff = (size_t)h * HDIM;

    uint32_t aqh[4][4], aql[4][4];
    {
        size_t qb = ((size_t)(b*SEQ) + row0) * EMB + hoff;
        #pragma unroll
        for (int ks = 0; ks < 4; ks++) {
            const __half* p = qh + qb + ks*16 + t4*2;
            aqh[ks][0] = *(const uint32_t*)p;
            aqh[ks][1] = *(const uint32_t*)(p + 8*EMB);
            aqh[ks][2] = *(const uint32_t*)(p + 8);
            aqh[ks][3] = *(const uint32_t*)(p + 8*EMB + 8);
            const __half* q2 = ql + qb + ks*16 + t4*2;
            aql[ks][0] = *(const uint32_t*)q2;
            aql[ks][1] = *(const uint32_t*)(q2 + 8*EMB);
            aql[ks][2] = *(const uint32_t*)(q2 + 8);
            aql[ks][3] = *(const uint32_t*)(q2 + 8*EMB + 8);
        }
    }

    auto issue = [&](int kt, int stg) {
        size_t kvb = ((size_t)(b*SEQ) + kt*64) * EMB + hoff;
        const char* srcs[2] = { (const char*)(khg + kvb), (const char*)(vhg + kvb) };
        uint32_t dstb = smb + stg * AT_STAGE;
        #pragma unroll
        for (int t = 0; t < 2; t++) {
            #pragma unroll
            for (int j = 0; j < 2; j++) {
                int idx = tid + j*256;
                int r = idx >> 3, c = idx & 7;
                cp16(dstb + t*AT_TILE + r*GPB + c*16, srcs[t] + (size_t)r*2048 + c*16);
            }
        }
        CP_COMMIT();
    };

    float accO[8][4] = {};
    float m0 = -1e30f, m1 = -1e30f, l0 = 0.0f, l1 = 0.0f;
    const float Cs = 0.125f * 1.4426950408889634f;

    const int ntiles = 2*qt + 2;
    const uint32_t vfragoff = (uint32_t)(((lane & 7) + ((lane >> 3) & 1)*8) * GPB + (lane >> 4)*16);

    issue(0, 0);
    for (int kt = 0; kt < ntiles; kt++) {
        int cur = kt & 1;
        if (kt + 1 < ntiles) { issue(kt + 1, cur ^ 1); CP_WAIT1(); }
        else                 { CP_WAIT0(); }
        __syncthreads();

        char* KH = sm + cur*AT_STAGE;
        const uint32_t vhb = smb + cur*AT_STAGE + AT_TILE + vfragoff;

        if (kt*64 <= row_base + 15) {
            // ---- S = (Qh+Ql) K^T ----
            float s[8][4] = {};
            #pragma unroll
            for (int ks = 0; ks < 4; ks++) {
                #pragma unroll
                for (int nt = 0; nt < 8; nt++) {
                    const char* p = KH + (nt*8+g)*GPB + ks*32 + t4*4;
                    uint32_t bh0 = *(const uint32_t*)p;
                    uint32_t bh1 = *(const uint32_t*)(p + 16);
                    mma16816(s[nt], aqh[ks], bh0, bh1);
                    mma16816(s[nt], aql[ks], bh0, bh1);
                }
            }
            // ---- mask + scale ----
            #pragma unroll
            for (int nt = 0; nt < 8; nt++) {
                int colb = kt*64 + nt*8 + t4*2;
                s[nt][0] = (colb     > row0) ? -3e28f : s[nt][0]*Cs;
                s[nt][1] = (colb + 1 > row0) ? -3e28f : s[nt][1]*Cs;
                s[nt][2] = (colb     > row1) ? -3e28f : s[nt][2]*Cs;
                s[nt][3] = (colb + 1 > row1) ? -3e28f : s[nt][3]*Cs;
            }
            // ---- row max ----
            float rm0 = -3e28f, rm1 = -3e28f;
            #pragma unroll
            for (int nt = 0; nt < 8; nt++) {
                rm0 = fmaxf(rm0, fmaxf(s[nt][0], s[nt][1]));
                rm1 = fmaxf(rm1, fmaxf(s[nt][2], s[nt][3]));
            }
            rm0 = fmaxf(rm0, __shfl_xor_sync(0xffffffffu, rm0, 1));
            rm0 = fmaxf(rm0, __shfl_xor_sync(0xffffffffu, rm0, 2));
            rm1 = fmaxf(rm1, __shfl_xor_sync(0xffffffffu, rm1, 1));
            rm1 = fmaxf(rm1, __shfl_xor_sync(0xffffffffu, rm1, 2));

            float mn0 = fmaxf(m0, rm0), mn1 = fmaxf(m1, rm1);
            float alpha0 = exp2f(m0 - mn0), alpha1 = exp2f(m1 - mn1);
            m0 = mn0; m1 = mn1;

            float sum0 = 0.0f, sum1 = 0.0f;
            uint32_t aph[4][4], apl[4][4];
            #pragma unroll
            for (int nt = 0; nt < 8; nt++) {
                float p0 = exp2f(s[nt][0] - m0);
                float p1 = exp2f(s[nt][1] - m0);
                float p2 = exp2f(s[nt][2] - m1);
                float p3 = exp2f(s[nt][3] - m1);
                sum0 += p0 + p1;  sum1 += p2 + p3;
                __half h0 = __float2half_rn(p0), h1b = __float2half_rn(p1);
                __half h2 = __float2half_rn(p2), h3b = __float2half_rn(p3);
                int kc = nt >> 1, odd = nt & 1;
                aph[kc][odd ? 2 : 0] = pack2h(h0, h1b);
                aph[kc][odd ? 3 : 1] = pack2h(h2, h3b);
                apl[kc][odd ? 2 : 0] = packh(p0 - __half2float(h0), p1 - __half2float(h1b));
                apl[kc][odd ? 3 : 1] = packh(p2 - __half2float(h2), p3 - __half2float(h3b));
            }
            sum0 += __shfl_xor_sync(0xffffffffu, sum0, 1);
            sum0 += __shfl_xor_sync(0xffffffffu, sum0, 2);
            sum1 += __shfl_xor_sync(0xffffffffu, sum1, 1);
            sum1 += __shfl_xor_sync(0xffffffffu, sum1, 2);
            l0 = l0 * alpha0 + sum0;
            l1 = l1 * alpha1 + sum1;

            #pragma unroll
            for (int nt = 0; nt < 8; nt++) {
                accO[nt][0] *= alpha0; accO[nt][1] *= alpha0;
                accO[nt][2] *= alpha1; accO[nt][3] *= alpha1;
            }
            // ---- O += (Ph+Pl) V, V via ldmatrix.trans ----
            #pragma unroll
            for (int ks = 0; ks < 4; ks++) {
                #pragma unroll
                for (int ntp = 0; ntp < 4; ntp++) {
                    uint32_t r0, r1, r2, r3;
                    ldsm4t(r0, r1, r2, r3, vhb + ks*16*GPB + ntp*32);
                    mma16816(accO[2*ntp],   aph[ks], r0, r1);
                    mma16816(accO[2*ntp+1], aph[ks], r2, r3);
                    mma16816(accO[2*ntp],   apl[ks], r0, r1);
                    mma16816(accO[2*ntp+1], apl[ks], r2, r3);
                }
            }
        }
        __syncthreads();
    }

    float inv0 = 1.0f / l0, inv1 = 1.0f / l1;
    size_t ob = ((size_t)(b*SEQ) + row0) * EMB + hoff;
    #pragma unroll
    for (int nt = 0; nt < 8; nt++) {
        store_split_h(ch, cl, ob + nt*8 + t4*2,          accO[nt][0]*inv0, accO[nt][1]*inv0);
        store_split_h(ch, cl, ob + 8*EMB + nt*8 + t4*2,  accO[nt][2]*inv1, accO[nt][3]*inv1);
    }
}

// ---------------------------------------------------------------------------
extern "C" void kernel_launch(void* const* d_in, const int* in_sizes, int n_in,
                              void* d_out, int out_size) {
    const float* x  = (const float*)d_in[0];
    const float* Wq = (const float*)d_in[1];
    const float* Wk = (const float*)d_in[2];
    const float* Wv = (const float*)d_in[3];
    const float* Wo = (const float*)d_in[4];
    float* out = (float*)d_out;

    __half *xh, *xl, *ch, *cl, *wh;
    __half *qhp, *qlp, *khp, *vhp;
    cudaGetSymbolAddress((void**)&xh, g_xh);
    cudaGetSymbolAddress((void**)&xl, g_xl);
    cudaGetSymbolAddress((void**)&ch, g_ch);
    cudaGetSymbolAddress((void**)&cl, g_cl);
    cudaGetSymbolAddress((void**)&wh, g_wh);
    cudaGetSymbolAddress((void**)&qhp, g_qh);
    cudaGetSymbolAddress((void**)&qlp, g_ql);
    cudaGetSymbolAddress((void**)&khp, g_kh);
    cudaGetSymbolAddress((void**)&vhp, g_vh);

    cudaFuncSetAttribute(gemm_qkv, cudaFuncAttributeMaxDynamicSharedMemorySize, GT_SMEM);
    cudaFuncSetAttribute(gemm_o,   cudaFuncAttributeMaxDynamicSharedMemorySize, GT_SMEM);
    cudaFuncSetAttribute(attn_mma, cudaFuncAttributeMaxDynamicSharedMemorySize, ATTN_SMEM);

    split_all<<<(NX4 + 4*NW4) / 256, 256>>>((const float4*)x,
        (const float4*)Wq, (const float4*)Wk, (const float4*)Wv, (const float4*)Wo,
        (__half2*)xh, (__half2*)xl, (__half2*)wh);

    gemm_qkv<<<dim3(EMB/128, NROWS/256, 3), 512, GT_SMEM>>>(
        xh, xl, wh, qhp, qlp, khp, vhp);

    attn_mma<<<dim3(SEQ/128, HEADS, BATCH), 256, ATTN_SMEM>>>(
        qhp, qlp, khp, vhp, ch, cl);

    gemm_o<<<dim3(EMB/128, NROWS/256), 512, GT_SMEM>>>(
        ch, cl, wh + 3*(size_t)EMB*EMB, out);
}

// round 16
// speedup vs baseline: 2.6605x; 1.1898x over previous
#include <cuda_runtime.h>
#include <cuda_fp16.h>
#include <cstdint>
#include <math.h>

#define BATCH 2
#define SEQ   2048
#define EMB   1024
#define HEADS 16
#define HDIM  64
#define NROWS (BATCH*SEQ)

// ---------------- scratch (__device__ globals; no allocs allowed) -----------
__device__ __half g_xh[NROWS*EMB], g_xl[NROWS*EMB];
__device__ __half g_ch[NROWS*EMB], g_cl[NROWS*EMB];
__device__ __half g_wh[4][EMB*EMB];
__device__ __half g_qh[NROWS*EMB];
__device__ __half g_kh[NROWS*EMB];
__device__ __half g_vh[NROWS*EMB];

// ---------------- helpers ----------------------------------------------------
__device__ __forceinline__ uint32_t smem_u32(const void* p) {
    uint32_t a;
    asm("{ .reg .u64 t; cvta.to.shared.u64 t, %1; cvt.u32.u64 %0, t; }" : "=r"(a) : "l"(p));
    return a;
}
__device__ __forceinline__ void mma16816(float* c, const uint32_t* a,
                                         uint32_t b0, uint32_t b1) {
    asm volatile(
        "mma.sync.aligned.m16n8k16.row.col.f32.f16.f16.f32 "
        "{%0,%1,%2,%3}, {%4,%5,%6,%7}, {%8,%9}, {%0,%1,%2,%3};"
        : "+f"(c[0]), "+f"(c[1]), "+f"(c[2]), "+f"(c[3])
        : "r"(a[0]), "r"(a[1]), "r"(a[2]), "r"(a[3]), "r"(b0), "r"(b1));
}
__device__ __forceinline__ void ldsm4t(uint32_t& r0, uint32_t& r1,
                                       uint32_t& r2, uint32_t& r3, uint32_t addr) {
    asm volatile("ldmatrix.sync.aligned.m8n8.x4.trans.shared.b16 {%0,%1,%2,%3}, [%4];"
        : "=r"(r0), "=r"(r1), "=r"(r2), "=r"(r3) : "r"(addr));
}
__device__ __forceinline__ void cp16(uint32_t dst, const void* src) {
    asm volatile("cp.async.cg.shared.global [%0], [%1], 16;" :: "r"(dst), "l"(src) : "memory");
}
#define CP_COMMIT() asm volatile("cp.async.commit_group;" ::: "memory")
#define CP_WAIT1()  asm volatile("cp.async.wait_group 1;" ::: "memory")
#define CP_WAIT0()  asm volatile("cp.async.wait_group 0;" ::: "memory")

__device__ __forceinline__ uint32_t pack2h(__half a, __half b) {
    __half2 t(a, b);
    return *reinterpret_cast<uint32_t*>(&t);
}
__device__ __forceinline__ void store_split_h(__half* oh, __half* ol,
                                              size_t idx, float v0, float v1) {
    __half h0 = __float2half_rn(v0), h1 = __float2half_rn(v1);
    *(__half2*)(oh + idx) = __half2(h0, h1);
    *(__half2*)(ol + idx) = __half2(
        __float2half_rn(v0 - __half2float(h0)),
        __float2half_rn(v1 - __half2float(h1)));
}
__device__ __forceinline__ void store_h(__half* oh, size_t idx, float v0, float v1) {
    *(__half2*)(oh + idx) = __floats2half2_rn(v0, v1);
}

// ---------------------------------------------------------------------------
// fused split: x (hi+lo fp16) + 4 weights (hi fp16 only) in ONE launch
// ---------------------------------------------------------------------------
#define NX4 (NROWS*EMB/4)     // 1048576
#define NW4 (EMB*EMB/4)       // 262144 = 2^18

__global__ __launch_bounds__(256) void split_all(const float4* __restrict__ x,
                                                 const float4* __restrict__ w0,
                                                 const float4* __restrict__ w1,
                                                 const float4* __restrict__ w2,
                                                 const float4* __restrict__ w3,
                                                 __half2* __restrict__ xh,
                                                 __half2* __restrict__ xl,
                                                 __half2* __restrict__ wh) {
    int i = blockIdx.x * blockDim.x + threadIdx.x;
    if (i < NX4) {
        float4 a = x[i];
        __half h0 = __float2half_rn(a.x), h1 = __float2half_rn(a.y);
        __half h2 = __float2half_rn(a.z), h3 = __float2half_rn(a.w);
        xh[i*2+0] = __half2(h0, h1);
        xh[i*2+1] = __half2(h2, h3);
        xl[i*2+0] = __half2(__float2half_rn(a.x - __half2float(h0)),
                            __float2half_rn(a.y - __half2float(h1)));
        xl[i*2+1] = __half2(__float2half_rn(a.z - __half2float(h2)),
                            __float2half_rn(a.w - __half2float(h3)));
    } else {
        int j = i - NX4;
        int wsel = j >> 18;
        int idx = j & (NW4 - 1);
        const float4* src = (wsel == 0) ? w0 : (wsel == 1) ? w1 : (wsel == 2) ? w2 : w3;
        __half2* oh = wh + (size_t)wsel * (EMB*EMB/2);
        float4 a = src[idx];
        oh[idx*2+0] = __floats2half2_rn(a.x, a.y);
        oh[idx*2+1] = __floats2half2_rn(a.z, a.w);
    }
}

// ---------------------------------------------------------------------------
// GEMM core: 256x128 CTA tile, 512 threads = 16 warps (8m x 2n), warp 32x64.
// fp16 2-pass: C = (Ah+Al)@Bh. k-chunk 64, cp.async double buffer.
// ---------------------------------------------------------------------------
#define GP    72
#define GPB   144
#define A_TILE2 (256*GPB)           // 36864 B
#define B_TILE2 (128*GPB)           // 18432 B
#define OFF_AH  0
#define OFF_AL  A_TILE2
#define OFF_BH  (2*A_TILE2)
#define GT_STAGE (2*A_TILE2 + B_TILE2)   // 92160 B
#define GT_SMEM  (2*GT_STAGE)            // 184320 B

__device__ __forceinline__ void gemm_core(const __half* __restrict__ Ah,
                                          const __half* __restrict__ Al,
                                          const __half* __restrict__ Bh,
                                          char* sm, uint32_t smb,
                                          int m0, int n0, float acc[2][8][4]) {
    const int tid = threadIdx.x;
    const int w = tid >> 5, lane = tid & 31, g = lane >> 2, t4 = lane & 3;
    const int wm = w & 7, wn = w >> 3;

    const char* gA[2] = { (const char*)(Ah + (size_t)m0 * EMB),
                          (const char*)(Al + (size_t)m0 * EMB) };
    const char* gB = (const char*)(Bh + (size_t)n0 * EMB);

    auto issue = [&](int kc, int stg) {
        uint32_t dstb = smb + stg * GT_STAGE;
        #pragma unroll
        for (int mX = 0; mX < 2; mX++) {
            const char* src = gA[mX] + kc * 128;
            #pragma unroll
            for (int j = 0; j < 4; j++) {
                int idx = tid + j * 512;        // 0..2047
                int r = idx >> 3, c = idx & 7;
                cp16(dstb + mX*A_TILE2 + r*GPB + c*16, src + (size_t)r*2048 + c*16);
            }
        }
        {
            const char* src = gB + kc * 128;
            #pragma unroll
            for (int j = 0; j < 2; j++) {
                int idx = tid + j * 512;        // 0..1023
                int r = idx >> 3, c = idx & 7;
                cp16(dstb + OFF_BH + r*GPB + c*16, src + (size_t)r*2048 + c*16);
            }
        }
        CP_COMMIT();
    };

    issue(0, 0);
    for (int kc = 0; kc < 16; kc++) {
        int cur = kc & 1;
        if (kc < 15) { issue(kc + 1, cur ^ 1); CP_WAIT1(); }
        else         { CP_WAIT0(); }
        __syncthreads();

        char* SAH = sm + cur*GT_STAGE + OFF_AH;
        char* SAL = sm + cur*GT_STAGE + OFF_AL;
        char* SBH = sm + cur*GT_STAGE + OFF_BH;

        #pragma unroll
        for (int ks = 0; ks < 4; ks++) {
            uint32_t ah[2][4], al[2][4];
            #pragma unroll
            for (int mt = 0; mt < 2; mt++) {
                int row = wm*32 + mt*16 + g;
                const char* p = SAH + row*GPB + ks*32 + t4*4;
                ah[mt][0] = *(const uint32_t*)p;
                ah[mt][1] = *(const uint32_t*)(p + 8*GPB);
                ah[mt][2] = *(const uint32_t*)(p + 16);
                ah[mt][3] = *(const uint32_t*)(p + 8*GPB + 16);
                const char* q = SAL + row*GPB + ks*32 + t4*4;
                al[mt][0] = *(const uint32_t*)q;
                al[mt][1] = *(const uint32_t*)(q + 8*GPB);
                al[mt][2] = *(const uint32_t*)(q + 16);
                al[mt][3] = *(const uint32_t*)(q + 8*GPB + 16);
            }
            #pragma unroll
            for (int nt = 0; nt < 8; nt++) {
                int brow = wn*64 + nt*8 + g;
                const char* p = SBH + brow*GPB + ks*32 + t4*4;
                uint32_t bh0 = *(const uint32_t*)p;
                uint32_t bh1 = *(const uint32_t*)(p + 16);
                mma16816(acc[0][nt], ah[0], bh0, bh1);
                mma16816(acc[1][nt], ah[1], bh0, bh1);
                mma16816(acc[0][nt], al[0], bh0, bh1);
                mma16816(acc[1][nt], al[1], bh0, bh1);
            }
        }
        __syncthreads();
    }
}

// ---------------------------------------------------------------------------
// Fused QKV: z=0 Q(rope, hi only), z=1 K(rope, hi only), z=2 V(hi only)
// ---------------------------------------------------------------------------
__global__ __launch_bounds__(512, 1) void gemm_qkv(const __half* __restrict__ xh,
                                                const __half* __restrict__ xl,
                                                const __half* __restrict__ wh,
                                                __half* __restrict__ qh,
                                                __half* __restrict__ kh,
                                                __half* __restrict__ vh) {
    extern __shared__ char sm[];
    const int z = blockIdx.z;
    const int n0 = blockIdx.x * 128, m0 = blockIdx.y * 256;
    float acc[2][8][4] = {};
    gemm_core(xh, xl, wh + (size_t)z*EMB*EMB, sm, smem_u32(sm), m0, n0, acc);

    const int tid = threadIdx.x;
    const int w = tid >> 5, lane = tid & 31, g = lane >> 2, t4 = lane & 3;
    const int wm = w & 7, wn = w >> 3;

    if (z < 2) {
        __half* oh = (z == 0) ? qh : kh;
        #pragma unroll
        for (int mt = 0; mt < 2; mt++) {
            int rbase = m0 + wm*32 + mt*16 + g;
            #pragma unroll
            for (int jr = 0; jr < 2; jr++) {
                int row = rbase + jr*8;
                int s = row & (SEQ - 1);
                #pragma unroll
                for (int nt = 0; nt < 4; nt++) {
                    int dbase = nt*8 + t4*2;
                    float o0[2], o1[2];
                    #pragma unroll
                    for (int jc = 0; jc < 2; jc++) {
                        int d = dbase + jc;
                        float inv = exp2f(-(float)(2*d) * (13.287712379549449f / 64.0f));
                        float sn, cs;
                        sincosf((float)s * inv, &sn, &cs);
                        float x1 = acc[mt][nt][jr*2+jc];
                        float x2 = acc[mt][nt+4][jr*2+jc];
                        o0[jc] = x1*cs - x2*sn;
                        o1[jc] = x2*cs + x1*sn;
                    }
                    size_t base = (size_t)row * EMB + n0 + wn*64 + dbase;
                    store_h(oh, base,      o0[0], o0[1]);
                    store_h(oh, base + 32, o1[0], o1[1]);
                }
            }
        }
    } else {
        #pragma unroll
        for (int mt = 0; mt < 2; mt++) {
            int row0 = m0 + wm*32 + mt*16 + g;
            #pragma unroll
            for (int nt = 0; nt < 8; nt++) {
                size_t base = (size_t)row0 * EMB + n0 + wn*64 + nt*8 + t4*2;
                store_h(vh, base,         acc[mt][nt][0], acc[mt][nt][1]);
                store_h(vh, base + 8*EMB, acc[mt][nt][2], acc[mt][nt][3]);
            }
        }
    }
}

// ---------------------------------------------------------------------------
// Output projection: (ch+cl)@Woh -> fp32 out
// ---------------------------------------------------------------------------
__global__ __launch_bounds__(512, 1) void gemm_o(const __half* __restrict__ Ah,
                                              const __half* __restrict__ Al,
                                              const __half* __restrict__ Bh,
                                              float* __restrict__ C) {
    extern __shared__ char sm[];
    const int n0 = blockIdx.x * 128, m0 = blockIdx.y * 256;
    float acc[2][8][4] = {};
    gemm_core(Ah, Al, Bh, sm, smem_u32(sm), m0, n0, acc);

    const int tid = threadIdx.x;
    const int w = tid >> 5, lane = tid & 31, g = lane >> 2, t4 = lane & 3;
    const int wm = w & 7, wn = w >> 3;
    #pragma unroll
    for (int mt = 0; mt < 2; mt++) {
        int row = m0 + wm*32 + mt*16 + g;
        #pragma unroll
        for (int nt = 0; nt < 8; nt++) {
            float* p0 = C + (size_t)row * EMB + n0 + wn*64 + nt*8 + t4*2;
            *(float2*)p0 = make_float2(acc[mt][nt][0], acc[mt][nt][1]);
            *(float2*)(p0 + 8*EMB) = make_float2(acc[mt][nt][2], acc[mt][nt][3]);
        }
    }
}

// ---------------------------------------------------------------------------
// fp16 flash attention, single-pass: S=Qh K^T, O=Ph V. K,V unsplit.
// Stage: KH | VH (64x144B each). Double buffered. Longest CTAs first.
// ---------------------------------------------------------------------------
#define AT_TILE  (64*GPB)           // 9216
#define AT_STAGE (2*AT_TILE)        // 18432
#define ATTN_SMEM (2*AT_STAGE)      // 36864

__global__ __launch_bounds__(256) void attn_mma(const __half* __restrict__ qh,
                                                const __half* __restrict__ khg,
                                                const __half* __restrict__ vhg,
                                                __half* __restrict__ ch,
                                                __half* __restrict__ cl) {
    extern __shared__ char sm[];
    const uint32_t smb = smem_u32(sm);

    const int tid = threadIdx.x;
    const int w = tid >> 5, lane = tid & 31, g = lane >> 2, t4 = lane & 3;
    const int qt = gridDim.x - 1 - blockIdx.x;   // longest CTAs first
    const int h = blockIdx.y, b = blockIdx.z;

    const int row_base = qt*128 + w*16;
    const int row0 = row_base + g;
    const int row1 = row0 + 8;
    const size_t hoff = (size_t)h * HDIM;

    uint32_t aqh[4][4];
    {
        size_t qb = ((size_t)(b*SEQ) + row0) * EMB + hoff;
        #pragma unroll
        for (int ks = 0; ks < 4; ks++) {
            const __half* p = qh + qb + ks*16 + t4*2;
            aqh[ks][0] = *(const uint32_t*)p;
            aqh[ks][1] = *(const uint32_t*)(p + 8*EMB);
            aqh[ks][2] = *(const uint32_t*)(p + 8);
            aqh[ks][3] = *(const uint32_t*)(p + 8*EMB + 8);
        }
    }

    auto issue = [&](int kt, int stg) {
        size_t kvb = ((size_t)(b*SEQ) + kt*64) * EMB + hoff;
        const char* srcs[2] = { (const char*)(khg + kvb), (const char*)(vhg + kvb) };
        uint32_t dstb = smb + stg * AT_STAGE;
        #pragma unroll
        for (int t = 0; t < 2; t++) {
            #pragma unroll
            for (int j = 0; j < 2; j++) {
                int idx = tid + j*256;
                int r = idx >> 3, c = idx & 7;
                cp16(dstb + t*AT_TILE + r*GPB + c*16, srcs[t] + (size_t)r*2048 + c*16);
            }
        }
        CP_COMMIT();
    };

    float accO[8][4] = {};
    float m0 = -1e30f, m1 = -1e30f, l0 = 0.0f, l1 = 0.0f;
    const float Cs = 0.125f * 1.4426950408889634f;

    const int ntiles = 2*qt + 2;
    const uint32_t vfragoff = (uint32_t)(((lane & 7) + ((lane >> 3) & 1)*8) * GPB + (lane >> 4)*16);

    issue(0, 0);
    for (int kt = 0; kt < ntiles; kt++) {
        int cur = kt & 1;
        if (kt + 1 < ntiles) { issue(kt + 1, cur ^ 1); CP_WAIT1(); }
        else                 { CP_WAIT0(); }
        __syncthreads();

        char* KH = sm + cur*AT_STAGE;
        const uint32_t vhb = smb + cur*AT_STAGE + AT_TILE + vfragoff;

        if (kt*64 <= row_base + 15) {
            // ---- S = Qh K^T ----
            float s[8][4] = {};
            #pragma unroll
            for (int ks = 0; ks < 4; ks++) {
                #pragma unroll
                for (int nt = 0; nt < 8; nt++) {
                    const char* p = KH + (nt*8+g)*GPB + ks*32 + t4*4;
                    uint32_t bh0 = *(const uint32_t*)p;
                    uint32_t bh1 = *(const uint32_t*)(p + 16);
                    mma16816(s[nt], aqh[ks], bh0, bh1);
                }
            }
            // ---- mask + scale ----
            #pragma unroll
            for (int nt = 0; nt < 8; nt++) {
                int colb = kt*64 + nt*8 + t4*2;
                s[nt][0] = (colb     > row0) ? -3e28f : s[nt][0]*Cs;
                s[nt][1] = (colb + 1 > row0) ? -3e28f : s[nt][1]*Cs;
                s[nt][2] = (colb     > row1) ? -3e28f : s[nt][2]*Cs;
                s[nt][3] = (colb + 1 > row1) ? -3e28f : s[nt][3]*Cs;
            }
            // ---- row max ----
            float rm0 = -3e28f, rm1 = -3e28f;
            #pragma unroll
            for (int nt = 0; nt < 8; nt++) {
                rm0 = fmaxf(rm0, fmaxf(s[nt][0], s[nt][1]));
                rm1 = fmaxf(rm1, fmaxf(s[nt][2], s[nt][3]));
            }
            rm0 = fmaxf(rm0, __shfl_xor_sync(0xffffffffu, rm0, 1));
            rm0 = fmaxf(rm0, __shfl_xor_sync(0xffffffffu, rm0, 2));
            rm1 = fmaxf(rm1, __shfl_xor_sync(0xffffffffu, rm1, 1));
            rm1 = fmaxf(rm1, __shfl_xor_sync(0xffffffffu, rm1, 2));

            float mn0 = fmaxf(m0, rm0), mn1 = fmaxf(m1, rm1);
            float alpha0 = exp2f(m0 - mn0), alpha1 = exp2f(m1 - mn1);
            m0 = mn0; m1 = mn1;

            float sum0 = 0.0f, sum1 = 0.0f;
            uint32_t aph[4][4];
            #pragma unroll
            for (int nt = 0; nt < 8; nt++) {
                float p0 = exp2f(s[nt][0] - m0);
                float p1 = exp2f(s[nt][1] - m0);
                float p2 = exp2f(s[nt][2] - m1);
                float p3 = exp2f(s[nt][3] - m1);
                sum0 += p0 + p1;  sum1 += p2 + p3;
                __half h0 = __float2half_rn(p0), h1b = __float2half_rn(p1);
                __half h2 = __float2half_rn(p2), h3b = __float2half_rn(p3);
                int kc = nt >> 1, odd = nt & 1;
                aph[kc][odd ? 2 : 0] = pack2h(h0, h1b);
                aph[kc][odd ? 3 : 1] = pack2h(h2, h3b);
            }
            sum0 += __shfl_xor_sync(0xffffffffu, sum0, 1);
            sum0 += __shfl_xor_sync(0xffffffffu, sum0, 2);
            sum1 += __shfl_xor_sync(0xffffffffu, sum1, 1);
            sum1 += __shfl_xor_sync(0xffffffffu, sum1, 2);
            l0 = l0 * alpha0 + sum0;
            l1 = l1 * alpha1 + sum1;

            #pragma unroll
            for (int nt = 0; nt < 8; nt++) {
                accO[nt][0] *= alpha0; accO[nt][1] *= alpha0;
                accO[nt][2] *= alpha1; accO[nt][3] *= alpha1;
            }
            // ---- O += Ph V, V via ldmatrix.trans ----
            #pragma unroll
            for (int ks = 0; ks < 4; ks++) {
                #pragma unroll
                for (int ntp = 0; ntp < 4; ntp++) {
                    uint32_t r0, r1, r2, r3;
                    ldsm4t(r0, r1, r2, r3, vhb + ks*16*GPB + ntp*32);
                    mma16816(accO[2*ntp],   aph[ks], r0, r1);
                    mma16816(accO[2*ntp+1], aph[ks], r2, r3);
                }
            }
        }
        __syncthreads();
    }

    float inv0 = 1.0f / l0, inv1 = 1.0f / l1;
    size_t ob = ((size_t)(b*SEQ) + row0) * EMB + hoff;
    #pragma unroll
    for (int nt = 0; nt < 8; nt++) {
        store_split_h(ch, cl, ob + nt*8 + t4*2,          accO[nt][0]*inv0, accO[nt][1]*inv0);
        store_split_h(ch, cl, ob + 8*EMB + nt*8 + t4*2,  accO[nt][2]*inv1, accO[nt][3]*inv1);
    }
}

// ---------------------------------------------------------------------------
extern "C" void kernel_launch(void* const* d_in, const int* in_sizes, int n_in,
                              void* d_out, int out_size) {
    const float* x  = (const float*)d_in[0];
    const float* Wq = (const float*)d_in[1];
    const float* Wk = (const float*)d_in[2];
    const float* Wv = (const float*)d_in[3];
    const float* Wo = (const float*)d_in[4];
    float* out = (float*)d_out;

    __half *xh, *xl, *ch, *cl, *wh;
    __half *qhp, *khp, *vhp;
    cudaGetSymbolAddress((void**)&xh, g_xh);
    cudaGetSymbolAddress((void**)&xl, g_xl);
    cudaGetSymbolAddress((void**)&ch, g_ch);
    cudaGetSymbolAddress((void**)&cl, g_cl);
    cudaGetSymbolAddress((void**)&wh, g_wh);
    cudaGetSymbolAddress((void**)&qhp, g_qh);
    cudaGetSymbolAddress((void**)&khp, g_kh);
    cudaGetSymbolAddress((void**)&vhp, g_vh);

    cudaFuncSetAttribute(gemm_qkv, cudaFuncAttributeMaxDynamicSharedMemorySize, GT_SMEM);
    cudaFuncSetAttribute(gemm_o,   cudaFuncAttributeMaxDynamicSharedMemorySize, GT_SMEM);
    cudaFuncSetAttribute(attn_mma, cudaFuncAttributeMaxDynamicSharedMemorySize, ATTN_SMEM);

    split_all<<<(NX4 + 4*NW4) / 256, 256>>>((const float4*)x,
        (const float4*)Wq, (const float4*)Wk, (const float4*)Wv, (const float4*)Wo,
        (__half2*)xh, (__half2*)xl, (__half2*)wh);

    gemm_qkv<<<dim3(EMB/128, NROWS/256, 3), 512, GT_SMEM>>>(
        xh, xl, wh, qhp, khp, vhp);

    attn_mma<<<dim3(SEQ/128, HEADS, BATCH), 256, ATTN_SMEM>>>(
        qhp, khp, vhp, ch, cl);

    gemm_o<<<dim3(EMB/128, NROWS/256), 512, GT_SMEM>>>(
        ch, cl, wh + 3*(size_t)EMB*EMB, out);
}

// round 17
// speedup vs baseline: 3.2753x; 1.2311x over previous
#include <cuda_runtime.h>
#include <cuda_fp16.h>
#include <cstdint>
#include <math.h>

#define BATCH 2
#define SEQ   2048
#define EMB   1024
#define HEADS 16
#define HDIM  64
#define NROWS (BATCH*SEQ)

// ---------------- scratch (__device__ globals; no allocs allowed) -----------
__device__ __half g_xh[NROWS*EMB];
__device__ __half g_ch[NROWS*EMB], g_cl[NROWS*EMB];
__device__ __half g_wh[4][EMB*EMB];
__device__ __half g_qh[NROWS*EMB];
__device__ __half g_kh[NROWS*EMB];
__device__ __half g_vh[NROWS*EMB];

// ---------------- helpers ----------------------------------------------------
__device__ __forceinline__ uint32_t smem_u32(const void* p) {
    uint32_t a;
    asm("{ .reg .u64 t; cvta.to.shared.u64 t, %1; cvt.u32.u64 %0, t; }" : "=r"(a) : "l"(p));
    return a;
}
__device__ __forceinline__ void mma16816(float* c, const uint32_t* a,
                                         uint32_t b0, uint32_t b1) {
    asm volatile(
        "mma.sync.aligned.m16n8k16.row.col.f32.f16.f16.f32 "
        "{%0,%1,%2,%3}, {%4,%5,%6,%7}, {%8,%9}, {%0,%1,%2,%3};"
        : "+f"(c[0]), "+f"(c[1]), "+f"(c[2]), "+f"(c[3])
        : "r"(a[0]), "r"(a[1]), "r"(a[2]), "r"(a[3]), "r"(b0), "r"(b1));
}
__device__ __forceinline__ void ldsm4t(uint32_t& r0, uint32_t& r1,
                                       uint32_t& r2, uint32_t& r3, uint32_t addr) {
    asm volatile("ldmatrix.sync.aligned.m8n8.x4.trans.shared.b16 {%0,%1,%2,%3}, [%4];"
        : "=r"(r0), "=r"(r1), "=r"(r2), "=r"(r3) : "r"(addr));
}
__device__ __forceinline__ void cp16(uint32_t dst, const void* src) {
    asm volatile("cp.async.cg.shared.global [%0], [%1], 16;" :: "r"(dst), "l"(src) : "memory");
}
#define CP_COMMIT() asm volatile("cp.async.commit_group;" ::: "memory")
#define CP_WAIT1()  asm volatile("cp.async.wait_group 1;" ::: "memory")
#define CP_WAIT0()  asm volatile("cp.async.wait_group 0;" ::: "memory")

__device__ __forceinline__ uint32_t pack2h(__half a, __half b) {
    __half2 t(a, b);
    return *reinterpret_cast<uint32_t*>(&t);
}
__device__ __forceinline__ void store_split_h(__half* oh, __half* ol,
                                              size_t idx, float v0, float v1) {
    __half h0 = __float2half_rn(v0), h1 = __float2half_rn(v1);
    *(__half2*)(oh + idx) = __half2(h0, h1);
    *(__half2*)(ol + idx) = __half2(
        __float2half_rn(v0 - __half2float(h0)),
        __float2half_rn(v1 - __half2float(h1)));
}
__device__ __forceinline__ void store_h(__half* oh, size_t idx, float v0, float v1) {
    *(__half2*)(oh + idx) = __floats2half2_rn(v0, v1);
}

// ---------------------------------------------------------------------------
// fused convert: x + 4 weights -> fp16 in ONE launch (no splits needed here)
// ---------------------------------------------------------------------------
#define NX4 (NROWS*EMB/4)     // 1048576
#define NW4 (EMB*EMB/4)       // 262144 = 2^18

__global__ __launch_bounds__(256) void split_all(const float4* __restrict__ x,
                                                 const float4* __restrict__ w0,
                                                 const float4* __restrict__ w1,
                                                 const float4* __restrict__ w2,
                                                 const float4* __restrict__ w3,
                                                 __half2* __restrict__ xh,
                                                 __half2* __restrict__ wh) {
    int i = blockIdx.x * blockDim.x + threadIdx.x;
    const float4* src; __half2* oh; int idx;
    if (i < NX4) {
        src = x; oh = xh; idx = i;
    } else {
        int j = i - NX4;
        int wsel = j >> 18;
        idx = j & (NW4 - 1);
        src = (wsel == 0) ? w0 : (wsel == 1) ? w1 : (wsel == 2) ? w2 : w3;
        oh = wh + (size_t)wsel * (EMB*EMB/2);
    }
    float4 a = src[idx];
    oh[idx*2+0] = __floats2half2_rn(a.x, a.y);
    oh[idx*2+1] = __floats2half2_rn(a.z, a.w);
}

// ---------------------------------------------------------------------------
// GEMM core: 256x128 CTA tile, 512 threads = 16 warps (8m x 2n), warp 32x64.
// Template: SA=true -> C=(Ah+Al)@Bh (2-pass); SA=false -> C=Ah@Bh (1-pass).
// k-chunk 64, cp.async double buffer.
// ---------------------------------------------------------------------------
#define GP    72
#define GPB   144
#define A_TILE2 (256*GPB)           // 36864 B
#define B_TILE2 (128*GPB)           // 18432 B
#define ST1 (A_TILE2 + B_TILE2)     // 55296
#define ST2 (2*A_TILE2 + B_TILE2)   // 92160
#define GT_SMEM1 (2*ST1)            // 110592
#define GT_SMEM2 (2*ST2)            // 184320

template<bool SA>
__device__ __forceinline__ void gemm_core(const __half* __restrict__ Ah,
                                          const __half* __restrict__ Al,
                                          const __half* __restrict__ Bh,
                                          char* sm, uint32_t smb,
                                          int m0, int n0, float acc[2][8][4]) {
    constexpr int STAGE = SA ? ST2 : ST1;
    constexpr int OFFB  = SA ? 2*A_TILE2 : A_TILE2;

    const int tid = threadIdx.x;
    const int w = tid >> 5, lane = tid & 31, g = lane >> 2, t4 = lane & 3;
    const int wm = w & 7, wn = w >> 3;

    const char* gAh = (const char*)(Ah + (size_t)m0 * EMB);
    const char* gAl = SA ? (const char*)(Al + (size_t)m0 * EMB) : nullptr;
    const char* gB  = (const char*)(Bh + (size_t)n0 * EMB);

    auto issue = [&](int kc, int stg) {
        uint32_t dstb = smb + stg * STAGE;
        {
            const char* src = gAh + kc * 128;
            #pragma unroll
            for (int j = 0; j < 4; j++) {
                int idx = tid + j * 512;
                int r = idx >> 3, c = idx & 7;
                cp16(dstb + r*GPB + c*16, src + (size_t)r*2048 + c*16);
            }
        }
        if (SA) {
            const char* src = gAl + kc * 128;
            #pragma unroll
            for (int j = 0; j < 4; j++) {
                int idx = tid + j * 512;
                int r = idx >> 3, c = idx & 7;
                cp16(dstb + A_TILE2 + r*GPB + c*16, src + (size_t)r*2048 + c*16);
            }
        }
        {
            const char* src = gB + kc * 128;
            #pragma unroll
            for (int j = 0; j < 2; j++) {
                int idx = tid + j * 512;
                int r = idx >> 3, c = idx & 7;
                cp16(dstb + OFFB + r*GPB + c*16, src + (size_t)r*2048 + c*16);
            }
        }
        CP_COMMIT();
    };

    issue(0, 0);
    for (int kc = 0; kc < 16; kc++) {
        int cur = kc & 1;
        if (kc < 15) { issue(kc + 1, cur ^ 1); CP_WAIT1(); }
        else         { CP_WAIT0(); }
        __syncthreads();

        char* SAH = sm + cur*STAGE;
        char* SAL = SAH + A_TILE2;
        char* SBH = SAH + OFFB;

        #pragma unroll
        for (int ks = 0; ks < 4; ks++) {
            uint32_t ah[2][4], al[2][4];
            #pragma unroll
            for (int mt = 0; mt < 2; mt++) {
                int row = wm*32 + mt*16 + g;
                const char* p = SAH + row*GPB + ks*32 + t4*4;
                ah[mt][0] = *(const uint32_t*)p;
                ah[mt][1] = *(const uint32_t*)(p + 8*GPB);
                ah[mt][2] = *(const uint32_t*)(p + 16);
                ah[mt][3] = *(const uint32_t*)(p + 8*GPB + 16);
                if (SA) {
                    const char* q = SAL + row*GPB + ks*32 + t4*4;
                    al[mt][0] = *(const uint32_t*)q;
                    al[mt][1] = *(const uint32_t*)(q + 8*GPB);
                    al[mt][2] = *(const uint32_t*)(q + 16);
                    al[mt][3] = *(const uint32_t*)(q + 8*GPB + 16);
                }
            }
            #pragma unroll
            for (int nt = 0; nt < 8; nt++) {
                int brow = wn*64 + nt*8 + g;
                const char* p = SBH + brow*GPB + ks*32 + t4*4;
                uint32_t bh0 = *(const uint32_t*)p;
                uint32_t bh1 = *(const uint32_t*)(p + 16);
                mma16816(acc[0][nt], ah[0], bh0, bh1);
                mma16816(acc[1][nt], ah[1], bh0, bh1);
                if (SA) {
                    mma16816(acc[0][nt], al[0], bh0, bh1);
                    mma16816(acc[1][nt], al[1], bh0, bh1);
                }
            }
        }
        __syncthreads();
    }
}

// ---------------------------------------------------------------------------
// Fused QKV (1-pass): z=0 Q(rope), z=1 K(rope), z=2 V
// ---------------------------------------------------------------------------
__global__ __launch_bounds__(512, 1) void gemm_qkv(const __half* __restrict__ xh,
                                                const __half* __restrict__ wh,
                                                __half* __restrict__ qh,
                                                __half* __restrict__ kh,
                                                __half* __restrict__ vh) {
    extern __shared__ char sm[];
    const int z = blockIdx.z;
    const int n0 = blockIdx.x * 128, m0 = blockIdx.y * 256;
    float acc[2][8][4] = {};
    gemm_core<false>(xh, nullptr, wh + (size_t)z*EMB*EMB, sm, smem_u32(sm), m0, n0, acc);

    const int tid = threadIdx.x;
    const int w = tid >> 5, lane = tid & 31, g = lane >> 2, t4 = lane & 3;
    const int wm = w & 7, wn = w >> 3;

    if (z < 2) {
        __half* oh = (z == 0) ? qh : kh;
        #pragma unroll
        for (int mt = 0; mt < 2; mt++) {
            int rbase = m0 + wm*32 + mt*16 + g;
            #pragma unroll
            for (int jr = 0; jr < 2; jr++) {
                int row = rbase + jr*8;
                int s = row & (SEQ - 1);
                #pragma unroll
                for (int nt = 0; nt < 4; nt++) {
                    int dbase = nt*8 + t4*2;
                    float o0[2], o1[2];
                    #pragma unroll
                    for (int jc = 0; jc < 2; jc++) {
                        int d = dbase + jc;
                        float inv = exp2f(-(float)(2*d) * (13.287712379549449f / 64.0f));
                        float sn, cs;
                        sincosf((float)s * inv, &sn, &cs);
                        float x1 = acc[mt][nt][jr*2+jc];
                        float x2 = acc[mt][nt+4][jr*2+jc];
                        o0[jc] = x1*cs - x2*sn;
                        o1[jc] = x2*cs + x1*sn;
                    }
                    size_t base = (size_t)row * EMB + n0 + wn*64 + dbase;
                    store_h(oh, base,      o0[0], o0[1]);
                    store_h(oh, base + 32, o1[0], o1[1]);
                }
            }
        }
    } else {
        #pragma unroll
        for (int mt = 0; mt < 2; mt++) {
            int row0 = m0 + wm*32 + mt*16 + g;
            #pragma unroll
            for (int nt = 0; nt < 8; nt++) {
                size_t base = (size_t)row0 * EMB + n0 + wn*64 + nt*8 + t4*2;
                store_h(vh, base,         acc[mt][nt][0], acc[mt][nt][1]);
                store_h(vh, base + 8*EMB, acc[mt][nt][2], acc[mt][nt][3]);
            }
        }
    }
}

// ---------------------------------------------------------------------------
// Output projection (2-pass): (ch+cl)@Woh -> fp32 out
// ---------------------------------------------------------------------------
__global__ __launch_bounds__(512, 1) void gemm_o(const __half* __restrict__ Ah,
                                              const __half* __restrict__ Al,
                                              const __half* __restrict__ Bh,
                                              float* __restrict__ C) {
    extern __shared__ char sm[];
    const int n0 = blockIdx.x * 128, m0 = blockIdx.y * 256;
    float acc[2][8][4] = {};
    gemm_core<true>(Ah, Al, Bh, sm, smem_u32(sm), m0, n0, acc);

    const int tid = threadIdx.x;
    const int w = tid >> 5, lane = tid & 31, g = lane >> 2, t4 = lane & 3;
    const int wm = w & 7, wn = w >> 3;
    #pragma unroll
    for (int mt = 0; mt < 2; mt++) {
        int row = m0 + wm*32 + mt*16 + g;
        #pragma unroll
        for (int nt = 0; nt < 8; nt++) {
            float* p0 = C + (size_t)row * EMB + n0 + wn*64 + nt*8 + t4*2;
            *(float2*)p0 = make_float2(acc[mt][nt][0], acc[mt][nt][1]);
            *(float2*)(p0 + 8*EMB) = make_float2(acc[mt][nt][2], acc[mt][nt][3]);
        }
    }
}

// ---------------------------------------------------------------------------
// fp16 flash attention, single-pass: S=Qh K^T, O=Ph V. (R16-proven)
// ---------------------------------------------------------------------------
#define AT_TILE  (64*GPB)           // 9216
#define AT_STAGE (2*AT_TILE)        // 18432
#define ATTN_SMEM (2*AT_STAGE)      // 36864

__global__ __launch_bounds__(256) void attn_mma(const __half* __restrict__ qh,
                                                const __half* __restrict__ khg,
                                                const __half* __restrict__ vhg,
                                                __half* __restrict__ ch,
                                                __half* __restrict__ cl) {
    extern __shared__ char sm[];
    const uint32_t smb = smem_u32(sm);

    const int tid = threadIdx.x;
    const int w = tid >> 5, lane = tid & 31, g = lane >> 2, t4 = lane & 3;
    const int qt = gridDim.x - 1 - blockIdx.x;   // longest CTAs first
    const int h = blockIdx.y, b = blockIdx.z;

    const int row_base = qt*128 + w*16;
    const int row0 = row_base + g;
    const int row1 = row0 + 8;
    const size_t hoff = (size_t)h * HDIM;

    uint32_t aqh[4][4];
    {
        size_t qb = ((size_t)(b*SEQ) + row0) * EMB + hoff;
        #pragma unroll
        for (int ks = 0; ks < 4; ks++) {
            const __half* p = qh + qb + ks*16 + t4*2;
            aqh[ks][0] = *(const uint32_t*)p;
            aqh[ks][1] = *(const uint32_t*)(p + 8*EMB);
            aqh[ks][2] = *(const uint32_t*)(p + 8);
            aqh[ks][3] = *(const uint32_t*)(p + 8*EMB + 8);
        }
    }

    auto issue = [&](int kt, int stg) {
        size_t kvb = ((size_t)(b*SEQ) + kt*64) * EMB + hoff;
        const char* srcs[2] = { (const char*)(khg + kvb), (const char*)(vhg + kvb) };
        uint32_t dstb = smb + stg * AT_STAGE;
        #pragma unroll
        for (int t = 0; t < 2; t++) {
            #pragma unroll
            for (int j = 0; j < 2; j++) {
                int idx = tid + j*256;
                int r = idx >> 3, c = idx & 7;
                cp16(dstb + t*AT_TILE + r*GPB + c*16, srcs[t] + (size_t)r*2048 + c*16);
            }
        }
        CP_COMMIT();
    };

    float accO[8][4] = {};
    float m0 = -1e30f, m1 = -1e30f, l0 = 0.0f, l1 = 0.0f;
    const float Cs = 0.125f * 1.4426950408889634f;

    const int ntiles = 2*qt + 2;
    const uint32_t vfragoff = (uint32_t)(((lane & 7) + ((lane >> 3) & 1)*8) * GPB + (lane >> 4)*16);

    issue(0, 0);
    for (int kt = 0; kt < ntiles; kt++) {
        int cur = kt & 1;
        if (kt + 1 < ntiles) { issue(kt + 1, cur ^ 1); CP_WAIT1(); }
        else                 { CP_WAIT0(); }
        __syncthreads();

        char* KH = sm + cur*AT_STAGE;
        const uint32_t vhb = smb + cur*AT_STAGE + AT_TILE + vfragoff;

        if (kt*64 <= row_base + 15) {
            // ---- S = Qh K^T ----
            float s[8][4] = {};
            #pragma unroll
            for (int ks = 0; ks < 4; ks++) {
                #pragma unroll
                for (int nt = 0; nt < 8; nt++) {
                    const char* p = KH + (nt*8+g)*GPB + ks*32 + t4*4;
                    uint32_t bh0 = *(const uint32_t*)p;
                    uint32_t bh1 = *(const uint32_t*)(p + 16);
                    mma16816(s[nt], aqh[ks], bh0, bh1);
                }
            }
            // ---- mask + scale ----
            #pragma unroll
            for (int nt = 0; nt < 8; nt++) {
                int colb = kt*64 + nt*8 + t4*2;
                s[nt][0] = (colb     > row0) ? -3e28f : s[nt][0]*Cs;
                s[nt][1] = (colb + 1 > row0) ? -3e28f : s[nt][1]*Cs;
                s[nt][2] = (colb     > row1) ? -3e28f : s[nt][2]*Cs;
                s[nt][3] = (colb + 1 > row1) ? -3e28f : s[nt][3]*Cs;
            }
            // ---- row max ----
            float rm0 = -3e28f, rm1 = -3e28f;
            #pragma unroll
            for (int nt = 0; nt < 8; nt++) {
                rm0 = fmaxf(rm0, fmaxf(s[nt][0], s[nt][1]));
                rm1 = fmaxf(rm1, fmaxf(s[nt][2], s[nt][3]));
            }
            rm0 = fmaxf(rm0, __shfl_xor_sync(0xffffffffu, rm0, 1));
            rm0 = fmaxf(rm0, __shfl_xor_sync(0xffffffffu, rm0, 2));
            rm1 = fmaxf(rm1, __shfl_xor_sync(0xffffffffu, rm1, 1));
            rm1 = fmaxf(rm1, __shfl_xor_sync(0xffffffffu, rm1, 2));

            float mn0 = fmaxf(m0, rm0), mn1 = fmaxf(m1, rm1);
            float alpha0 = exp2f(m0 - mn0), alpha1 = exp2f(m1 - mn1);
            m0 = mn0; m1 = mn1;

            float sum0 = 0.0f, sum1 = 0.0f;
            uint32_t aph[4][4];
            #pragma unroll
            for (int nt = 0; nt < 8; nt++) {
                float p0 = exp2f(s[nt][0] - m0);
                float p1 = exp2f(s[nt][1] - m0);
                float p2 = exp2f(s[nt][2] - m1);
                float p3 = exp2f(s[nt][3] - m1);
                sum0 += p0 + p1;  sum1 += p2 + p3;
                __half h0 = __float2half_rn(p0), h1b = __float2half_rn(p1);
                __half h2 = __float2half_rn(p2), h3b = __float2half_rn(p3);
                int kc = nt >> 1, odd = nt & 1;
                aph[kc][odd ? 2 : 0] = pack2h(h0, h1b);
                aph[kc][odd ? 3 : 1] = pack2h(h2, h3b);
            }
            sum0 += __shfl_xor_sync(0xffffffffu, sum0, 1);
            sum0 += __shfl_xor_sync(0xffffffffu, sum0, 2);
            sum1 += __shfl_xor_sync(0xffffffffu, sum1, 1);
            sum1 += __shfl_xor_sync(0xffffffffu, sum1, 2);
            l0 = l0 * alpha0 + sum0;
            l1 = l1 * alpha1 + sum1;

            #pragma unroll
            for (int nt = 0; nt < 8; nt++) {
                accO[nt][0] *= alpha0; accO[nt][1] *= alpha0;
                accO[nt][2] *= alpha1; accO[nt][3] *= alpha1;
            }
            // ---- O += Ph V, V via ldmatrix.trans ----
            #pragma unroll
            for (int ks = 0; ks < 4; ks++) {
                #pragma unroll
                for (int ntp = 0; ntp < 4; ntp++) {
                    uint32_t r0, r1, r2, r3;
                    ldsm4t(r0, r1, r2, r3, vhb + ks*16*GPB + ntp*32);
                    mma16816(accO[2*ntp],   aph[ks], r0, r1);
                    mma16816(accO[2*ntp+1], aph[ks], r2, r3);
                }
            }
        }
        __syncthreads();
    }

    float inv0 = 1.0f / l0, inv1 = 1.0f / l1;
    size_t ob = ((size_t)(b*SEQ) + row0) * EMB + hoff;
    #pragma unroll
    for (int nt = 0; nt < 8; nt++) {
        store_split_h(ch, cl, ob + nt*8 + t4*2,          accO[nt][0]*inv0, accO[nt][1]*inv0);
        store_split_h(ch, cl, ob + 8*EMB + nt*8 + t4*2,  accO[nt][2]*inv1, accO[nt][3]*inv1);
    }
}

// ---------------------------------------------------------------------------
extern "C" void kernel_launch(void* const* d_in, const int* in_sizes, int n_in,
                              void* d_out, int out_size) {
    const float* x  = (const float*)d_in[0];
    const float* Wq = (const float*)d_in[1];
    const float* Wk = (const float*)d_in[2];
    const float* Wv = (const float*)d_in[3];
    const float* Wo = (const float*)d_in[4];
    float* out = (float*)d_out;

    __half *xh, *ch, *cl, *wh;
    __half *qhp, *khp, *vhp;
    cudaGetSymbolAddress((void**)&xh, g_xh);
    cudaGetSymbolAddress((void**)&ch, g_ch);
    cudaGetSymbolAddress((void**)&cl, g_cl);
    cudaGetSymbolAddress((void**)&wh, g_wh);
    cudaGetSymbolAddress((void**)&qhp, g_qh);
    cudaGetSymbolAddress((void**)&khp, g_kh);
    cudaGetSymbolAddress((void**)&vhp, g_vh);

    cudaFuncSetAttribute(gemm_qkv, cudaFuncAttributeMaxDynamicSharedMemorySize, GT_SMEM1);
    cudaFuncSetAttribute(gemm_o,   cudaFuncAttributeMaxDynamicSharedMemorySize, GT_SMEM2);
    cudaFuncSetAttribute(attn_mma, cudaFuncAttributeMaxDynamicSharedMemorySize, ATTN_SMEM);

    split_all<<<(NX4 + 4*NW4) / 256, 256>>>((const float4*)x,
        (const float4*)Wq, (const float4*)Wk, (const float4*)Wv, (const float4*)Wo,
        (__half2*)xh, (__half2*)wh);

    gemm_qkv<<<dim3(EMB/128, NROWS/256, 3), 512, GT_SMEM1>>>(
        xh, wh, qhp, khp, vhp);

    attn_mma<<<dim3(SEQ/128, HEADS, BATCH), 256, ATTN_SMEM>>>(
        qhp, khp, vhp, ch, cl);

    gemm_o<<<dim3(EMB/128, NROWS/256), 512, GT_SMEM2>>>(
        ch, cl, wh + 3*(size_t)EMB*EMB, out);
}